// round 13
// baseline (speedup 1.0000x reference)
#include <cuda_runtime.h>
#include <cuda_bf16.h>
#include <math_constants.h>
#include <stdint.h>

#define B_ 128
#define T_ 512
#define D_ 400
#define DP_ 416                 // padded K (pad is zero-initialized, never written)
#define V_ 1024
#define A_ 128

#define KC      32              // K elems per chunk (two m16n8k16 steps)
#define NCHUNK  13              // 13*32 = 416
#define STRIDEW 20              // words per row (16 data + 4 pad), conflict-free
#define REG_WORDS   (128 * STRIDEW)
#define STAGE_WORDS (4 * REG_WORDS)     // Ahi, Alo, Bhi, Blo
#define STAGE_BYTES (STAGE_WORDS * 4)   // 40960
#define NSTAGE 2
#define SMEM_WORDS  (NSTAGE * STAGE_WORDS + 512 + 1024 + 512)
#define SMEM_BYTES  (SMEM_WORDS * 4)    // 90112

#define N_ITEMS (B_ * 8)        // 1024 work items (b, v-tile)
#define GRID_PERSIST 296        // 2 CTAs/SM x 148 SMs

// -------- scratch (device globals; zero-initialized at load) ---------------
__device__ __align__(256) __nv_bfloat16 g_Hhi[B_ * T_ * DP_];
__device__ __align__(256) __nv_bfloat16 g_Hlo[B_ * T_ * DP_];
__device__ __align__(256) __nv_bfloat16 g_Vhi[V_ * DP_];
__device__ __align__(256) __nv_bfloat16 g_Vlo[V_ * DP_];
__device__ float g_hW[B_ * T_];
__device__ float g_p[B_ * A_];
__device__ float g_q[B_ * D_];
__device__ int   g_ctr;

// ======================= helpers ===========================================
__device__ __forceinline__ uint32_t smem_u32(const void* p) {
    uint32_t a;
    asm("{ .reg .u64 t; cvta.to.shared.u64 t, %1; cvt.u32.u64 %0, t; }"
        : "=r"(a) : "l"(p));
    return a;
}
#define CP_ASYNC16(dst, src) \
    asm volatile("cp.async.cg.shared.global [%0], [%1], 16;" \
                 :: "r"(dst), "l"(src) : "memory")
#define CP_COMMIT() asm volatile("cp.async.commit_group;" ::: "memory")
#define CP_WAIT0()  asm volatile("cp.async.wait_group 0;" ::: "memory")

#define LDSM_X4(R, addr)                                                      \
    asm volatile("ldmatrix.sync.aligned.m8n8.x4.shared.b16 {%0,%1,%2,%3}, [%4];" \
        : "=r"((R)[0]), "=r"((R)[1]), "=r"((R)[2]), "=r"((R)[3]) : "r"(addr))

__device__ __forceinline__ void mma16(float d[4], const uint32_t a[4],
                                      const uint32_t b0, const uint32_t b1) {
    asm volatile(
        "mma.sync.aligned.m16n8k16.row.col.f32.bf16.bf16.f32 "
        "{%0,%1,%2,%3}, {%4,%5,%6,%7}, {%8,%9}, {%0,%1,%2,%3};"
        : "+f"(d[0]), "+f"(d[1]), "+f"(d[2]), "+f"(d[3])
        : "r"(a[0]), "r"(a[1]), "r"(a[2]), "r"(a[3]), "r"(b0), "r"(b1));
}

// ======================= counter reset =====================================
__global__ void reset_ctr_kernel() { g_ctr = 0; }

// ============ prep: H -> bf16 hi/lo split AND hW = H.W (warp per row) ======
__global__ __launch_bounds__(256) void prep_h_kernel(const float* __restrict__ H,
                                                     const float* __restrict__ W,
                                                     const int* __restrict__ lens) {
    __shared__ float sW[D_];
    for (int d = threadIdx.x; d < D_; d += 256) sW[d] = W[d];
    __syncthreads();

    const int wid = threadIdx.x >> 5, lane = threadIdx.x & 31;
    const size_t row = (size_t)blockIdx.x * 8 + wid;
    const int t = (int)(row & (T_ - 1));
    const int b = (int)(row >> 9);
    if (t >= lens[b]) return;                 // whole warp exits together

    const float* src = H + row * D_;
    float s = 0.f;
    for (int d4 = lane; d4 < D_ / 4; d4 += 32) {
        float4 x = ((const float4*)src)[d4];
        __nv_bfloat16 h[4], l[4];
        h[0] = __float2bfloat16_rn(x.x); l[0] = __float2bfloat16_rn(x.x - __bfloat162float(h[0]));
        h[1] = __float2bfloat16_rn(x.y); l[1] = __float2bfloat16_rn(x.y - __bfloat162float(h[1]));
        h[2] = __float2bfloat16_rn(x.z); l[2] = __float2bfloat16_rn(x.z - __bfloat162float(h[2]));
        h[3] = __float2bfloat16_rn(x.w); l[3] = __float2bfloat16_rn(x.w - __bfloat162float(h[3]));
        *(uint2*)(g_Hhi + row * DP_ + d4 * 4) = *(const uint2*)h;
        *(uint2*)(g_Hlo + row * DP_ + d4 * 4) = *(const uint2*)l;
        const float* w = sW + d4 * 4;
        s += x.x * w[0] + x.y * w[1] + x.z * w[2] + x.w * w[3];
    }
#pragma unroll
    for (int o = 16; o; o >>= 1) s += __shfl_xor_sync(0xffffffffu, s, o);
    if (lane == 0) g_hW[row] = s;
}

// ======================= V: bf16 hi/lo split (warp per row) ================
__global__ __launch_bounds__(256) void split_v_kernel(const float* __restrict__ src) {
    const int wid = threadIdx.x >> 5, lane = threadIdx.x & 31;
    const size_t v = (size_t)blockIdx.x * 8 + wid;
    const float* s = src + v * D_;
    for (int d4 = lane; d4 < D_ / 4; d4 += 32) {
        float4 x = ((const float4*)s)[d4];
        __nv_bfloat16 h[4], l[4];
        h[0] = __float2bfloat16_rn(x.x); l[0] = __float2bfloat16_rn(x.x - __bfloat162float(h[0]));
        h[1] = __float2bfloat16_rn(x.y); l[1] = __float2bfloat16_rn(x.y - __bfloat162float(h[1]));
        h[2] = __float2bfloat16_rn(x.z); l[2] = __float2bfloat16_rn(x.z - __bfloat162float(h[2]));
        h[3] = __float2bfloat16_rn(x.w); l[3] = __float2bfloat16_rn(x.w - __bfloat162float(h[3]));
        *(uint2*)(g_Vhi + v * DP_ + d4 * 4) = *(const uint2*)h;
        *(uint2*)(g_Vlo + v * DP_ + d4 * 4) = *(const uint2*)l;
    }
}

// ======================= fused scores GEMM + softmax =======================
// R9 inner loop (proven), persistent-CTA work stealing over 1024 items.
__global__ __launch_bounds__(256, 2) void fused_kernel(const int* __restrict__ lens,
                                                       const float* __restrict__ b_score,
                                                       float* __restrict__ y_utts) {
    extern __shared__ float sm[];
    float* hs = sm + NSTAGE * STAGE_WORDS;               // 512
    float4* part = (float4*)(hs + 512);                  // 256 float4
    float4* run  = part + 256;                           // 128 float4
    __shared__ int s_item;
    const uint32_t sbase = smem_u32(sm);

    const int tid = threadIdx.x, lane = tid & 31, wid = tid >> 5;
    const int g = lane >> 2, tig = lane & 3;
    const int warpM = wid & 3, warpN = wid >> 2;
    const float bsc = b_score[0];

    // ---- ldmatrix per-thread offsets (item-independent) ----
    const int arow = lane & 15;
    const int acol = (lane >> 4) * 4;
    uint32_t aoff[2];
#pragma unroll
    for (int mt = 0; mt < 2; mt++)
        aoff[mt] = sbase + ((warpM * 32 + mt * 16 + arow) * STRIDEW + acol) * 4;
    const int brow = (lane & 7) + ((lane >> 4) & 1) * 8;
    const int bcol = ((lane >> 3) & 1) * 4;
    uint32_t boff[4];
#pragma unroll
    for (int p = 0; p < 4; p++)
        boff[p] = sbase + ((warpN * 64 + p * 16 + brow) * STRIDEW + bcol) * 4;

    const int crow = tid >> 1, ch = tid & 1;
    const uint32_t dst0 = sbase + (crow * STRIDEW + ch * 8) * 4;

    while (true) {
        if (tid == 0) s_item = atomicAdd(&g_ctr, 1);
        __syncthreads();
        const int item = s_item;
        if (item >= N_ITEMS) break;
        const int b = item >> 3;
        const int v0 = (item & 7) * 128;
        const int len_b = lens[b];
        const int n_tiles = (len_b + 127) >> 7;
        const int total_c = n_tiles * NCHUNK;

        // ---- per-item copy sources ----
        const __nv_bfloat16* pAh = g_Vhi + (size_t)(v0 + crow) * DP_ + ch * 16;
        const __nv_bfloat16* pAl = g_Vlo + (size_t)(v0 + crow) * DP_ + ch * 16;
        const __nv_bfloat16* pBh = g_Hhi + (size_t)(b * T_ + crow) * DP_ + ch * 16;
        const __nv_bfloat16* pBl = g_Hlo + (size_t)(b * T_ + crow) * DP_ + ch * 16;

        int cp_t = 0, cp_k = 0;
#define COPY_NEXT(ST) do {                                                     \
        uint32_t _d = dst0 + (ST) * STAGE_BYTES;                               \
        size_t _o = (size_t)cp_t * DP_ + cp_k;                                 \
        CP_ASYNC16(_d,                          pAh + cp_k);                   \
        CP_ASYNC16(_d + 16,                     pAh + cp_k + 8);               \
        CP_ASYNC16(_d + REG_WORDS * 4,          pAl + cp_k);                   \
        CP_ASYNC16(_d + REG_WORDS * 4 + 16,     pAl + cp_k + 8);               \
        CP_ASYNC16(_d + 2 * REG_WORDS * 4,      pBh + _o);                     \
        CP_ASYNC16(_d + 2 * REG_WORDS * 4 + 16, pBh + _o + 8);                 \
        CP_ASYNC16(_d + 3 * REG_WORDS * 4,      pBl + _o);                     \
        CP_ASYNC16(_d + 3 * REG_WORDS * 4 + 16, pBl + _o + 8);                 \
        cp_k += KC; if (cp_k == DP_) { cp_k = 0; cp_t += 128; }                \
    } while (0)

        COPY_NEXT(0); CP_COMMIT();

        for (int i = tid; i < T_; i += 256) hs[i] = g_hW[b * T_ + i];
        if (tid < 128) run[tid] = make_float4(-CUDART_INF_F, 0.f, 0.f, 0.f);
        __syncthreads();

        int fc = 0;
        for (int tt = 0; tt < n_tiles; tt++) {
            const int t0 = tt * 128;

            float acc[2][8][4];
#pragma unroll
            for (int mt = 0; mt < 2; mt++)
#pragma unroll
                for (int nt = 0; nt < 8; nt++)
#pragma unroll
                    for (int r = 0; r < 4; r++) acc[mt][nt][r] = 0.f;

            for (int kc = 0; kc < NCHUNK; kc++, fc++) {
                CP_WAIT0();
                __syncthreads();
                if (fc + 1 < total_c) COPY_NEXT((fc + 1) & 1);
                CP_COMMIT();

                const uint32_t so = (fc & 1) * STAGE_BYTES;
#pragma unroll
                for (int s = 0; s < 2; s++) {
                    const uint32_t so2 = so + s * 32;     // +8 words per k-step
                    uint32_t ah[2][4], al[2][4], bb[4][4];
#pragma unroll
                    for (int mt = 0; mt < 2; mt++) {
                        LDSM_X4(ah[mt], aoff[mt] + so2);
                        LDSM_X4(al[mt], aoff[mt] + so2 + REG_WORDS * 4);
                    }
#pragma unroll
                    for (int p = 0; p < 4; p++)
                        LDSM_X4(bb[p], boff[p] + so2 + 2 * REG_WORDS * 4);
                    // ---- pass 1: hi*hi ----
#pragma unroll
                    for (int nt = 0; nt < 8; nt++) {
                        const uint32_t b0 = bb[nt >> 1][(nt & 1) * 2];
                        const uint32_t b1 = bb[nt >> 1][(nt & 1) * 2 + 1];
#pragma unroll
                        for (int mt = 0; mt < 2; mt++)
                            mma16(acc[mt][nt], ah[mt], b0, b1);
                    }
                    // ---- pass 2: lo*hi ----
#pragma unroll
                    for (int nt = 0; nt < 8; nt++) {
                        const uint32_t b0 = bb[nt >> 1][(nt & 1) * 2];
                        const uint32_t b1 = bb[nt >> 1][(nt & 1) * 2 + 1];
#pragma unroll
                        for (int mt = 0; mt < 2; mt++)
                            mma16(acc[mt][nt], al[mt], b0, b1);
                    }
                    // ---- pass 3: hi*lo ----
#pragma unroll
                    for (int p = 0; p < 4; p++)
                        LDSM_X4(bb[p], boff[p] + so2 + 3 * REG_WORDS * 4);
#pragma unroll
                    for (int nt = 0; nt < 8; nt++) {
                        const uint32_t b0 = bb[nt >> 1][(nt & 1) * 2];
                        const uint32_t b1 = bb[nt >> 1][(nt & 1) * 2 + 1];
#pragma unroll
                        for (int mt = 0; mt < 2; mt++)
                            mma16(acc[mt][nt], ah[mt], b0, b1);
                    }
                }
            }

            // ---- epilogue: masked softmax partials ----
#pragma unroll
            for (int mt = 0; mt < 2; mt++)
#pragma unroll
                for (int rh = 0; rh < 2; rh++) {
                    float m = -CUDART_INF_F;
#pragma unroll
                    for (int nt = 0; nt < 8; nt++)
#pragma unroll
                        for (int j2 = 0; j2 < 2; j2++) {
                            int tc = t0 + warpN * 64 + nt * 8 + 2 * tig + j2;
                            float x = acc[mt][nt][rh * 2 + j2];
                            m = fmaxf(m, tc < len_b ? x : -CUDART_INF_F);
                        }
                    m = fmaxf(m, __shfl_xor_sync(0xffffffffu, m, 1));
                    m = fmaxf(m, __shfl_xor_sync(0xffffffffu, m, 2));
                    float l = 0.f, w = 0.f;
#pragma unroll
                    for (int nt = 0; nt < 8; nt++)
#pragma unroll
                        for (int j2 = 0; j2 < 2; j2++) {
                            int tc = t0 + warpN * 64 + nt * 8 + 2 * tig + j2;
                            if (tc < len_b) {
                                float e = __expf(acc[mt][nt][rh * 2 + j2] - m);
                                l += e;
                                w += e * hs[tc];
                            }
                        }
                    l += __shfl_xor_sync(0xffffffffu, l, 1);
                    l += __shfl_xor_sync(0xffffffffu, l, 2);
                    w += __shfl_xor_sync(0xffffffffu, w, 1);
                    w += __shfl_xor_sync(0xffffffffu, w, 2);
                    if (tig == 0) {
                        int row = warpM * 32 + mt * 16 + g + rh * 8;
                        part[row * 2 + warpN] = make_float4(m, l, w, 0.f);
                    }
                }
            __syncthreads();
            if (tid < 128) {
                float4 r = run[tid];
                float4 p0 = part[tid * 2 + 0];
                float4 p1 = part[tid * 2 + 1];
                float nm = fmaxf(r.x, fmaxf(p0.x, p1.x));
                float er = __expf(r.x - nm);
                float e0 = __expf(p0.x - nm);
                float e1 = __expf(p1.x - nm);
                r.y = r.y * er + p0.y * e0 + p1.y * e1;
                r.z = r.z * er + p0.z * e0 + p1.z * e1;
                r.x = nm;
                run[tid] = r;
            }
            __syncthreads();
        }

        if (tid < 128)
            y_utts[b * V_ + v0 + tid] = run[tid].z / run[tid].y + bsc;
        __syncthreads();   // hs/run reused by next item
#undef COPY_NEXT
    }
}

// ======================= acts: s2 dot (warp per (b,a)) =====================
__global__ __launch_bounds__(256) void acts_s2_kernel(const float* __restrict__ C_acts,
                                                      const float* __restrict__ c_utt) {
    const int gw = blockIdx.x * 8 + (threadIdx.x >> 5);
    const int lane = threadIdx.x & 31;
    const int b = gw >> 7, a = gw & 127;
    const float4* cr = (const float4*)(C_acts + ((size_t)b * A_ + a) * D_);
    const float4* cu = (const float4*)(c_utt + (size_t)b * D_);
    float s = 0.f;
    for (int i = lane; i < D_ / 4; i += 32) {
        float4 x = cr[i], y = cu[i];
        s += x.x * y.x + x.y * y.y + x.z * y.z + x.w * y.w;
    }
#pragma unroll
    for (int o = 16; o; o >>= 1) s += __shfl_xor_sync(0xffffffffu, s, o);
    if (lane == 0) g_p[gw] = s;
}

// ======================= acts: softmax over a ==============================
__global__ __launch_bounds__(128) void acts_softmax_kernel() {
    __shared__ float w4[4], w4b[4];
    const int b = blockIdx.x;
    const int tid = threadIdx.x;
    const int warp = tid >> 5, lane = tid & 31;
    float s = g_p[b * A_ + tid];
    float m = s;
#pragma unroll
    for (int o = 16; o; o >>= 1) m = fmaxf(m, __shfl_xor_sync(0xffffffffu, m, o));
    if (lane == 0) w4[warp] = m;
    __syncthreads();
    m = fmaxf(fmaxf(w4[0], w4[1]), fmaxf(w4[2], w4[3]));
    float e = __expf(s - m);
    float smv = e;
#pragma unroll
    for (int o = 16; o; o >>= 1) smv += __shfl_xor_sync(0xffffffffu, smv, o);
    if (lane == 0) w4b[warp] = smv;
    __syncthreads();
    float tot = w4b[0] + w4b[1] + w4b[2] + w4b[3];
    g_p[b * A_ + tid] = e / tot;
}

// ======================= acts phase B: q = p @ C_acts ======================
__global__ __launch_bounds__(128) void acts_q_kernel(const float* __restrict__ C_acts) {
    __shared__ float p[A_];
    const int b = blockIdx.y;
    const int d = blockIdx.x * 100 + threadIdx.x;
    if (threadIdx.x < A_) p[threadIdx.x] = g_p[b * A_ + threadIdx.x];
    __syncthreads();
    if (threadIdx.x >= 100) return;
    const float* Cb = C_acts + (size_t)b * A_ * D_ + d;
    float q = 0.f;
#pragma unroll 4
    for (int a = 0; a < A_; a++) q = fmaf(p[a], Cb[(size_t)a * D_], q);
    g_q[b * D_ + d] = q;
}

// ======================= y_acts: warp per v-row ============================
__global__ __launch_bounds__(256) void yacts_kernel(const float* __restrict__ vals,
                                                    float* __restrict__ y_acts) {
    __shared__ float qs[16 * D_];
    const int tid = threadIdx.x, lane = tid & 31, wid = tid >> 5;
    const int b0 = blockIdx.y * 16;
    const int v = blockIdx.x * 8 + wid;

    for (int f = tid; f < 16 * D_; f += 256) qs[f] = g_q[b0 * D_ + f];
    __syncthreads();

    float acc[16];
#pragma unroll
    for (int bb = 0; bb < 16; bb++) acc[bb] = 0.f;

    const float4* vr = (const float4*)(vals + (size_t)v * D_);
    const float4* q4 = (const float4*)qs;
    for (int d4 = lane; d4 < D_ / 4; d4 += 32) {
        float4 r = vr[d4];
#pragma unroll
        for (int bb = 0; bb < 16; bb++) {
            float4 q = q4[bb * (D_ / 4) + d4];
            acc[bb] += r.x * q.x + r.y * q.y + r.z * q.z + r.w * q.w;
        }
    }
#pragma unroll
    for (int o = 16; o; o >>= 1)
#pragma unroll
        for (int bb = 0; bb < 16; bb++)
            acc[bb] += __shfl_xor_sync(0xffffffffu, acc[bb], o);
    if (lane == 0) {
#pragma unroll
        for (int bb = 0; bb < 16; bb++)
            y_acts[(size_t)(b0 + bb) * V_ + v] = acc[bb];
    }
}

// ===========================================================================
extern "C" void kernel_launch(void* const* d_in, const int* in_sizes, int n_in,
                              void* d_out, int out_size) {
    const float* H       = (const float*)d_in[0];
    const float* c_utt   = (const float*)d_in[1];
    const float* C_acts  = (const float*)d_in[2];
    const float* C_vals  = (const float*)d_in[3];
    const float* W       = (const float*)d_in[4];
    const float* b_score = (const float*)d_in[5];
    const int*   lens    = (const int*)d_in[6];

    float* y_utts = (float*)d_out;
    float* y_acts = (float*)d_out + (size_t)B_ * V_;

    static cudaStream_t s_side = nullptr;
    static cudaEvent_t ev_fork = nullptr, ev_join = nullptr;
    if (!s_side) {
        cudaStreamCreateWithFlags(&s_side, cudaStreamNonBlocking);
        cudaEventCreateWithFlags(&ev_fork, cudaEventDisableTiming);
        cudaEventCreateWithFlags(&ev_join, cudaEventDisableTiming);
        cudaFuncSetAttribute(fused_kernel,
                             cudaFuncAttributeMaxDynamicSharedMemorySize, SMEM_BYTES);
    }

    // fork: acts chain runs concurrently with prep + fused
    cudaEventRecord(ev_fork, 0);
    cudaStreamWaitEvent(s_side, ev_fork, 0);

    reset_ctr_kernel<<<1, 1>>>();
    prep_h_kernel<<<(B_ * T_) / 8, 256>>>(H, W, lens);
    split_v_kernel<<<V_ / 8, 256>>>(C_vals);
    fused_kernel<<<GRID_PERSIST, 256, SMEM_BYTES>>>(lens, b_score, y_utts);

    acts_s2_kernel<<<B_ * A_ / 8, 256, 0, s_side>>>(C_acts, c_utt);
    acts_softmax_kernel<<<B_, 128, 0, s_side>>>();
    acts_q_kernel<<<dim3(4, B_), 128, 0, s_side>>>(C_acts);
    yacts_kernel<<<dim3(V_ / 8, B_ / 16), 256, 0, s_side>>>(C_vals, y_acts);

    // join
    cudaEventRecord(ev_join, s_side);
    cudaStreamWaitEvent(0, ev_join, 0);
}

// round 14
// speedup vs baseline: 1.0917x; 1.0917x over previous
#include <cuda_runtime.h>
#include <cuda_bf16.h>
#include <math_constants.h>
#include <stdint.h>

#define B_ 128
#define T_ 512
#define D_ 400
#define DP_ 416                 // padded K (pad is zero-initialized, never written)
#define V_ 1024
#define A_ 128

#define KC      32              // K elems per chunk (two m16n8k16 steps)
#define NCHUNK  13              // 13*32 = 416
#define STRIDEW 20              // words per row (16 data + 4 pad), conflict-free
#define REG_WORDS   (128 * STRIDEW)
#define STAGE_WORDS (4 * REG_WORDS)     // Ahi, Alo, Bhi, Blo
#define STAGE_BYTES (STAGE_WORDS * 4)   // 40960
#define NSTAGE 2
#define SMEM_WORDS  (NSTAGE * STAGE_WORDS + 512 + 1024 + 512)
#define SMEM_BYTES  (SMEM_WORDS * 4)    // 90112

// -------- scratch (device globals; zero-initialized at load) ---------------
__device__ __align__(256) __nv_bfloat16 g_Hhi[B_ * T_ * DP_];
__device__ __align__(256) __nv_bfloat16 g_Hlo[B_ * T_ * DP_];
__device__ __align__(256) __nv_bfloat16 g_Vhi[V_ * DP_];
__device__ __align__(256) __nv_bfloat16 g_Vlo[V_ * DP_];
__device__ float g_hW[B_ * T_];
__device__ float g_p[B_ * A_];
__device__ float g_q[B_ * D_];

// ======================= helpers ===========================================
__device__ __forceinline__ uint32_t smem_u32(const void* p) {
    uint32_t a;
    asm("{ .reg .u64 t; cvta.to.shared.u64 t, %1; cvt.u32.u64 %0, t; }"
        : "=r"(a) : "l"(p));
    return a;
}
#define CP_ASYNC16(dst, src) \
    asm volatile("cp.async.cg.shared.global [%0], [%1], 16;" \
                 :: "r"(dst), "l"(src) : "memory")
#define CP_COMMIT() asm volatile("cp.async.commit_group;" ::: "memory")
#define CP_WAIT0()  asm volatile("cp.async.wait_group 0;" ::: "memory")

#define LDSM_X4(R, addr)                                                      \
    asm volatile("ldmatrix.sync.aligned.m8n8.x4.shared.b16 {%0,%1,%2,%3}, [%4];" \
        : "=r"((R)[0]), "=r"((R)[1]), "=r"((R)[2]), "=r"((R)[3]) : "r"(addr))

__device__ __forceinline__ void mma16(float d[4], const uint32_t a[4],
                                      const uint32_t b0, const uint32_t b1) {
    asm volatile(
        "mma.sync.aligned.m16n8k16.row.col.f32.bf16.bf16.f32 "
        "{%0,%1,%2,%3}, {%4,%5,%6,%7}, {%8,%9}, {%0,%1,%2,%3};"
        : "+f"(d[0]), "+f"(d[1]), "+f"(d[2]), "+f"(d[3])
        : "r"(a[0]), "r"(a[1]), "r"(a[2]), "r"(a[3]), "r"(b0), "r"(b1));
}

// ============ prep: H -> bf16 hi/lo split AND hW = H.W (warp per row) ======
__global__ __launch_bounds__(256) void prep_h_kernel(const float* __restrict__ H,
                                                     const float* __restrict__ W,
                                                     const int* __restrict__ lens) {
    __shared__ float sW[D_];
    for (int d = threadIdx.x; d < D_; d += 256) sW[d] = W[d];
    __syncthreads();

    const int wid = threadIdx.x >> 5, lane = threadIdx.x & 31;
    const size_t row = (size_t)blockIdx.x * 8 + wid;
    const int t = (int)(row & (T_ - 1));
    const int b = (int)(row >> 9);
    if (t >= lens[b]) return;                 // whole warp exits together

    const float* src = H + row * D_;
    float s = 0.f;
    for (int d4 = lane; d4 < D_ / 4; d4 += 32) {
        float4 x = ((const float4*)src)[d4];
        __nv_bfloat16 h[4], l[4];
        h[0] = __float2bfloat16_rn(x.x); l[0] = __float2bfloat16_rn(x.x - __bfloat162float(h[0]));
        h[1] = __float2bfloat16_rn(x.y); l[1] = __float2bfloat16_rn(x.y - __bfloat162float(h[1]));
        h[2] = __float2bfloat16_rn(x.z); l[2] = __float2bfloat16_rn(x.z - __bfloat162float(h[2]));
        h[3] = __float2bfloat16_rn(x.w); l[3] = __float2bfloat16_rn(x.w - __bfloat162float(h[3]));
        *(uint2*)(g_Hhi + row * DP_ + d4 * 4) = *(const uint2*)h;
        *(uint2*)(g_Hlo + row * DP_ + d4 * 4) = *(const uint2*)l;
        const float* w = sW + d4 * 4;
        s += x.x * w[0] + x.y * w[1] + x.z * w[2] + x.w * w[3];
    }
#pragma unroll
    for (int o = 16; o; o >>= 1) s += __shfl_xor_sync(0xffffffffu, s, o);
    if (lane == 0) g_hW[row] = s;
}

// ======================= V: bf16 hi/lo split (warp per row) ================
__global__ __launch_bounds__(256) void split_v_kernel(const float* __restrict__ src) {
    const int wid = threadIdx.x >> 5, lane = threadIdx.x & 31;
    const size_t v = (size_t)blockIdx.x * 8 + wid;
    const float* s = src + v * D_;
    for (int d4 = lane; d4 < D_ / 4; d4 += 32) {
        float4 x = ((const float4*)s)[d4];
        __nv_bfloat16 h[4], l[4];
        h[0] = __float2bfloat16_rn(x.x); l[0] = __float2bfloat16_rn(x.x - __bfloat162float(h[0]));
        h[1] = __float2bfloat16_rn(x.y); l[1] = __float2bfloat16_rn(x.y - __bfloat162float(h[1]));
        h[2] = __float2bfloat16_rn(x.z); l[2] = __float2bfloat16_rn(x.z - __bfloat162float(h[2]));
        h[3] = __float2bfloat16_rn(x.w); l[3] = __float2bfloat16_rn(x.w - __bfloat162float(h[3]));
        *(uint2*)(g_Vhi + v * DP_ + d4 * 4) = *(const uint2*)h;
        *(uint2*)(g_Vlo + v * DP_ + d4 * 4) = *(const uint2*)l;
    }
}

// ======================= fused scores GEMM + softmax =======================
// R9 config; chunk body reordered: barrier -> LDSM -> pass1 -> copy-issue ->
// pass2/3. Copies hide under tensor drain instead of delaying fragment loads.
__global__ __launch_bounds__(256, 2) void fused_kernel(const int* __restrict__ lens,
                                                       const float* __restrict__ b_score,
                                                       float* __restrict__ y_utts) {
    extern __shared__ float sm[];
    float* hs = sm + NSTAGE * STAGE_WORDS;               // 512
    float4* part = (float4*)(hs + 512);                  // 256 float4
    float4* run  = part + 256;                           // 128 float4
    const uint32_t sbase = smem_u32(sm);

    const int tid = threadIdx.x, lane = tid & 31, wid = tid >> 5;
    const int g = lane >> 2, tig = lane & 3;
    const int warpM = wid & 3, warpN = wid >> 2;
    const int b = blockIdx.y, v0 = blockIdx.x * 128;
    const int len_b = lens[b];
    const float bsc = b_score[0];
    const int n_tiles = (len_b + 127) >> 7;
    const int total_c = n_tiles * NCHUNK;

    for (int i = tid; i < T_; i += 256) hs[i] = g_hW[b * T_ + i];
    if (tid < 128) run[tid] = make_float4(-CUDART_INF_F, 0.f, 0.f, 0.f);
    __syncthreads();

    // ---- per-thread copy sources: 2 threads/row, each covers 16 elems ----
    const int crow = tid >> 1, ch = tid & 1;
    const __nv_bfloat16* pAh = g_Vhi + (size_t)(v0 + crow) * DP_ + ch * 16;
    const __nv_bfloat16* pAl = g_Vlo + (size_t)(v0 + crow) * DP_ + ch * 16;
    const __nv_bfloat16* pBh = g_Hhi + (size_t)(b * T_ + crow) * DP_ + ch * 16;
    const __nv_bfloat16* pBl = g_Hlo + (size_t)(b * T_ + crow) * DP_ + ch * 16;
    const uint32_t dst0 = sbase + (crow * STRIDEW + ch * 8) * 4;

    int cp_t = 0, cp_k = 0;
#define COPY_NEXT(ST) do {                                                     \
        uint32_t _d = dst0 + (ST) * STAGE_BYTES;                               \
        size_t _o = (size_t)cp_t * DP_ + cp_k;                                 \
        CP_ASYNC16(_d,                          pAh + cp_k);                   \
        CP_ASYNC16(_d + 16,                     pAh + cp_k + 8);               \
        CP_ASYNC16(_d + REG_WORDS * 4,          pAl + cp_k);                   \
        CP_ASYNC16(_d + REG_WORDS * 4 + 16,     pAl + cp_k + 8);               \
        CP_ASYNC16(_d + 2 * REG_WORDS * 4,      pBh + _o);                     \
        CP_ASYNC16(_d + 2 * REG_WORDS * 4 + 16, pBh + _o + 8);                 \
        CP_ASYNC16(_d + 3 * REG_WORDS * 4,      pBl + _o);                     \
        CP_ASYNC16(_d + 3 * REG_WORDS * 4 + 16, pBl + _o + 8);                 \
        cp_k += KC; if (cp_k == DP_) { cp_k = 0; cp_t += 128; }                \
    } while (0)

    // ---- ldmatrix per-thread offsets ----
    const int arow = lane & 15;
    const int acol = (lane >> 4) * 4;
    uint32_t aoff[2];
#pragma unroll
    for (int mt = 0; mt < 2; mt++)
        aoff[mt] = sbase + ((warpM * 32 + mt * 16 + arow) * STRIDEW + acol) * 4;
    const int brow = (lane & 7) + ((lane >> 4) & 1) * 8;
    const int bcol = ((lane >> 3) & 1) * 4;
    uint32_t boff[4];
#pragma unroll
    for (int p = 0; p < 4; p++)
        boff[p] = sbase + ((warpN * 64 + p * 16 + brow) * STRIDEW + bcol) * 4;

    COPY_NEXT(0); CP_COMMIT();

    int fc = 0;
    for (int tt = 0; tt < n_tiles; tt++) {
        const int t0 = tt * 128;

        float acc[2][8][4];
#pragma unroll
        for (int mt = 0; mt < 2; mt++)
#pragma unroll
            for (int nt = 0; nt < 8; nt++)
#pragma unroll
                for (int r = 0; r < 4; r++) acc[mt][nt][r] = 0.f;

        for (int kc = 0; kc < NCHUNK; kc++, fc++) {
            CP_WAIT0();                       // chunk fc landed (this thread)
            __syncthreads();                  // all threads' chunk fc visible

            const uint32_t so = (fc & 1) * STAGE_BYTES;
            const int do_copy = (fc + 1 < total_c);
#pragma unroll
            for (int s = 0; s < 2; s++) {
                const uint32_t so2 = so + s * 32;     // +8 words per k-step
                uint32_t ah[2][4], al[2][4], bb[4][4];
#pragma unroll
                for (int mt = 0; mt < 2; mt++) {
                    LDSM_X4(ah[mt], aoff[mt] + so2);
                    LDSM_X4(al[mt], aoff[mt] + so2 + REG_WORDS * 4);
                }
#pragma unroll
                for (int p = 0; p < 4; p++)
                    LDSM_X4(bb[p], boff[p] + so2 + 2 * REG_WORDS * 4);
                // ---- pass 1: hi*hi ----
#pragma unroll
                for (int nt = 0; nt < 8; nt++) {
                    const uint32_t b0 = bb[nt >> 1][(nt & 1) * 2];
                    const uint32_t b1 = bb[nt >> 1][(nt & 1) * 2 + 1];
#pragma unroll
                    for (int mt = 0; mt < 2; mt++)
                        mma16(acc[mt][nt], ah[mt], b0, b1);
                }
                // ---- copy next chunk (only once, after s=0 pass 1):
                // LSU issue hides under tensor drain of pass 1.
                if (s == 0) {
                    if (do_copy) COPY_NEXT((fc + 1) & 1);
                    CP_COMMIT();
                }
                // ---- pass 2: lo*hi ----
#pragma unroll
                for (int nt = 0; nt < 8; nt++) {
                    const uint32_t b0 = bb[nt >> 1][(nt & 1) * 2];
                    const uint32_t b1 = bb[nt >> 1][(nt & 1) * 2 + 1];
#pragma unroll
                    for (int mt = 0; mt < 2; mt++)
                        mma16(acc[mt][nt], al[mt], b0, b1);
                }
                // ---- pass 3: hi*lo ----
#pragma unroll
                for (int p = 0; p < 4; p++)
                    LDSM_X4(bb[p], boff[p] + so2 + 3 * REG_WORDS * 4);
#pragma unroll
                for (int nt = 0; nt < 8; nt++) {
                    const uint32_t b0 = bb[nt >> 1][(nt & 1) * 2];
                    const uint32_t b1 = bb[nt >> 1][(nt & 1) * 2 + 1];
#pragma unroll
                    for (int mt = 0; mt < 2; mt++)
                        mma16(acc[mt][nt], ah[mt], b0, b1);
                }
            }
        }

        // ---- epilogue: masked softmax partials ----
#pragma unroll
        for (int mt = 0; mt < 2; mt++)
#pragma unroll
            for (int rh = 0; rh < 2; rh++) {
                float m = -CUDART_INF_F;
#pragma unroll
                for (int nt = 0; nt < 8; nt++)
#pragma unroll
                    for (int j2 = 0; j2 < 2; j2++) {
                        int tc = t0 + warpN * 64 + nt * 8 + 2 * tig + j2;
                        float x = acc[mt][nt][rh * 2 + j2];
                        m = fmaxf(m, tc < len_b ? x : -CUDART_INF_F);
                    }
                m = fmaxf(m, __shfl_xor_sync(0xffffffffu, m, 1));
                m = fmaxf(m, __shfl_xor_sync(0xffffffffu, m, 2));
                float l = 0.f, w = 0.f;
#pragma unroll
                for (int nt = 0; nt < 8; nt++)
#pragma unroll
                    for (int j2 = 0; j2 < 2; j2++) {
                        int tc = t0 + warpN * 64 + nt * 8 + 2 * tig + j2;
                        if (tc < len_b) {
                            float e = __expf(acc[mt][nt][rh * 2 + j2] - m);
                            l += e;
                            w += e * hs[tc];
                        }
                    }
                l += __shfl_xor_sync(0xffffffffu, l, 1);
                l += __shfl_xor_sync(0xffffffffu, l, 2);
                w += __shfl_xor_sync(0xffffffffu, w, 1);
                w += __shfl_xor_sync(0xffffffffu, w, 2);
                if (tig == 0) {
                    int row = warpM * 32 + mt * 16 + g + rh * 8;
                    part[row * 2 + warpN] = make_float4(m, l, w, 0.f);
                }
            }
        __syncthreads();
        if (tid < 128) {
            float4 r = run[tid];
            float4 p0 = part[tid * 2 + 0];
            float4 p1 = part[tid * 2 + 1];
            float nm = fmaxf(r.x, fmaxf(p0.x, p1.x));
            float er = __expf(r.x - nm);
            float e0 = __expf(p0.x - nm);
            float e1 = __expf(p1.x - nm);
            r.y = r.y * er + p0.y * e0 + p1.y * e1;
            r.z = r.z * er + p0.z * e0 + p1.z * e1;
            r.x = nm;
            run[tid] = r;
        }
        // no trailing barrier: part is rewritten only after the next tile's
        // k-loop (13 chunk barriers in between); run is per-thread private.
    }

    if (tid < 128)
        y_utts[b * V_ + v0 + tid] = run[tid].z / run[tid].y + bsc;
#undef COPY_NEXT
}

// ======================= acts: s2 dot (warp per (b,a)) =====================
__global__ __launch_bounds__(256) void acts_s2_kernel(const float* __restrict__ C_acts,
                                                      const float* __restrict__ c_utt) {
    const int gw = blockIdx.x * 8 + (threadIdx.x >> 5);
    const int lane = threadIdx.x & 31;
    const int b = gw >> 7, a = gw & 127;
    const float4* cr = (const float4*)(C_acts + ((size_t)b * A_ + a) * D_);
    const float4* cu = (const float4*)(c_utt + (size_t)b * D_);
    float s = 0.f;
    for (int i = lane; i < D_ / 4; i += 32) {
        float4 x = cr[i], y = cu[i];
        s += x.x * y.x + x.y * y.y + x.z * y.z + x.w * y.w;
    }
#pragma unroll
    for (int o = 16; o; o >>= 1) s += __shfl_xor_sync(0xffffffffu, s, o);
    if (lane == 0) g_p[gw] = s;
}

// ======================= acts: softmax over a ==============================
__global__ __launch_bounds__(128) void acts_softmax_kernel() {
    __shared__ float w4[4], w4b[4];
    const int b = blockIdx.x;
    const int tid = threadIdx.x;
    const int warp = tid >> 5, lane = tid & 31;
    float s = g_p[b * A_ + tid];
    float m = s;
#pragma unroll
    for (int o = 16; o; o >>= 1) m = fmaxf(m, __shfl_xor_sync(0xffffffffu, m, o));
    if (lane == 0) w4[warp] = m;
    __syncthreads();
    m = fmaxf(fmaxf(w4[0], w4[1]), fmaxf(w4[2], w4[3]));
    float e = __expf(s - m);
    float smv = e;
#pragma unroll
    for (int o = 16; o; o >>= 1) smv += __shfl_xor_sync(0xffffffffu, smv, o);
    if (lane == 0) w4b[warp] = smv;
    __syncthreads();
    float tot = w4b[0] + w4b[1] + w4b[2] + w4b[3];
    g_p[b * A_ + tid] = e / tot;
}

// ======================= acts phase B: q = p @ C_acts ======================
__global__ __launch_bounds__(128) void acts_q_kernel(const float* __restrict__ C_acts) {
    __shared__ float p[A_];
    const int b = blockIdx.y;
    const int d = blockIdx.x * 100 + threadIdx.x;
    if (threadIdx.x < A_) p[threadIdx.x] = g_p[b * A_ + threadIdx.x];
    __syncthreads();
    if (threadIdx.x >= 100) return;
    const float* Cb = C_acts + (size_t)b * A_ * D_ + d;
    float q = 0.f;
#pragma unroll 4
    for (int a = 0; a < A_; a++) q = fmaf(p[a], Cb[(size_t)a * D_], q);
    g_q[b * D_ + d] = q;
}

// ======================= y_acts: warp per v-row ============================
__global__ __launch_bounds__(256) void yacts_kernel(const float* __restrict__ vals,
                                                    float* __restrict__ y_acts) {
    __shared__ float qs[16 * D_];
    const int tid = threadIdx.x, lane = tid & 31, wid = tid >> 5;
    const int b0 = blockIdx.y * 16;
    const int v = blockIdx.x * 8 + wid;

    for (int f = tid; f < 16 * D_; f += 256) qs[f] = g_q[b0 * D_ + f];
    __syncthreads();

    float acc[16];
#pragma unroll
    for (int bb = 0; bb < 16; bb++) acc[bb] = 0.f;

    const float4* vr = (const float4*)(vals + (size_t)v * D_);
    const float4* q4 = (const float4*)qs;
    for (int d4 = lane; d4 < D_ / 4; d4 += 32) {
        float4 r = vr[d4];
#pragma unroll
        for (int bb = 0; bb < 16; bb++) {
            float4 q = q4[bb * (D_ / 4) + d4];
            acc[bb] += r.x * q.x + r.y * q.y + r.z * q.z + r.w * q.w;
        }
    }
#pragma unroll
    for (int o = 16; o; o >>= 1)
#pragma unroll
        for (int bb = 0; bb < 16; bb++)
            acc[bb] += __shfl_xor_sync(0xffffffffu, acc[bb], o);
    if (lane == 0) {
#pragma unroll
        for (int bb = 0; bb < 16; bb++)
            y_acts[(size_t)(b0 + bb) * V_ + v] = acc[bb];
    }
}

// ===========================================================================
extern "C" void kernel_launch(void* const* d_in, const int* in_sizes, int n_in,
                              void* d_out, int out_size) {
    const float* H       = (const float*)d_in[0];
    const float* c_utt   = (const float*)d_in[1];
    const float* C_acts  = (const float*)d_in[2];
    const float* C_vals  = (const float*)d_in[3];
    const float* W       = (const float*)d_in[4];
    const float* b_score = (const float*)d_in[5];
    const int*   lens    = (const int*)d_in[6];

    float* y_utts = (float*)d_out;
    float* y_acts = (float*)d_out + (size_t)B_ * V_;

    static cudaStream_t s_side = nullptr;
    static cudaEvent_t ev_fork = nullptr, ev_join = nullptr;
    if (!s_side) {
        cudaStreamCreateWithFlags(&s_side, cudaStreamNonBlocking);
        cudaEventCreateWithFlags(&ev_fork, cudaEventDisableTiming);
        cudaEventCreateWithFlags(&ev_join, cudaEventDisableTiming);
        cudaFuncSetAttribute(fused_kernel,
                             cudaFuncAttributeMaxDynamicSharedMemorySize, SMEM_BYTES);
    }

    // fork: acts chain runs concurrently with prep + fused
    cudaEventRecord(ev_fork, 0);
    cudaStreamWaitEvent(s_side, ev_fork, 0);

    prep_h_kernel<<<(B_ * T_) / 8, 256>>>(H, W, lens);
    split_v_kernel<<<V_ / 8, 256>>>(C_vals);
    fused_kernel<<<dim3(V_ / 128, B_), 256, SMEM_BYTES>>>(lens, b_score, y_utts);

    acts_s2_kernel<<<B_ * A_ / 8, 256, 0, s_side>>>(C_acts, c_utt);
    acts_softmax_kernel<<<B_, 128, 0, s_side>>>();
    acts_q_kernel<<<dim3(4, B_), 128, 0, s_side>>>(C_acts);
    yacts_kernel<<<dim3(V_ / 8, B_ / 16), 256, 0, s_side>>>(C_vals, y_acts);

    // join
    cudaEventRecord(ev_join, s_side);
    cudaStreamWaitEvent(0, ev_join, 0);
}

// round 15
// speedup vs baseline: 1.2032x; 1.1021x over previous
#include <cuda_runtime.h>
#include <cuda_bf16.h>
#include <math_constants.h>
#include <stdint.h>

#define B_ 128
#define T_ 512
#define D_ 400
#define DP_ 416                 // padded K (pad is zero-initialized, never written)
#define V_ 1024
#define A_ 128

#define KC      32              // K elems per chunk (two m16n8k16 steps)
#define NCHUNK  13              // 13*32 = 416
#define STRIDEW 20              // words per row (16 data + 4 pad), conflict-free
#define REG_WORDS   (128 * STRIDEW)
#define STAGE_WORDS (4 * REG_WORDS)     // Ahi, Alo, Bhi, Blo
#define STAGE_BYTES (STAGE_WORDS * 4)   // 40960
#define NSTAGE 2
#define SMEM_WORDS  (NSTAGE * STAGE_WORDS + 512 + 1024 + 512)
#define SMEM_BYTES  (SMEM_WORDS * 4)    // 90112

// -------- scratch (device globals; zero-initialized at load) ---------------
__device__ __align__(256) __nv_bfloat16 g_Hhi[B_ * T_ * DP_];
__device__ __align__(256) __nv_bfloat16 g_Hlo[B_ * T_ * DP_];
__device__ __align__(256) __nv_bfloat16 g_Vhi[V_ * DP_];
__device__ __align__(256) __nv_bfloat16 g_Vlo[V_ * DP_];
__device__ float g_hW[B_ * T_];
__device__ float g_p[B_ * A_];
__device__ float g_q[B_ * D_];
__device__ int   g_perm[B_];

// ======================= helpers ===========================================
__device__ __forceinline__ uint32_t smem_u32(const void* p) {
    uint32_t a;
    asm("{ .reg .u64 t; cvta.to.shared.u64 t, %1; cvt.u32.u64 %0, t; }"
        : "=r"(a) : "l"(p));
    return a;
}
#define CP_ASYNC16(dst, src) \
    asm volatile("cp.async.cg.shared.global [%0], [%1], 16;" \
                 :: "r"(dst), "l"(src) : "memory")
#define CP_COMMIT() asm volatile("cp.async.commit_group;" ::: "memory")
#define CP_WAIT0()  asm volatile("cp.async.wait_group 0;" ::: "memory")

#define LDSM_X4(R, addr)                                                      \
    asm volatile("ldmatrix.sync.aligned.m8n8.x4.shared.b16 {%0,%1,%2,%3}, [%4];" \
        : "=r"((R)[0]), "=r"((R)[1]), "=r"((R)[2]), "=r"((R)[3]) : "r"(addr))

__device__ __forceinline__ void mma16(float d[4], const uint32_t a[4],
                                      const uint32_t b0, const uint32_t b1) {
    asm volatile(
        "mma.sync.aligned.m16n8k16.row.col.f32.bf16.bf16.f32 "
        "{%0,%1,%2,%3}, {%4,%5,%6,%7}, {%8,%9}, {%0,%1,%2,%3};"
        : "+f"(d[0]), "+f"(d[1]), "+f"(d[2]), "+f"(d[3])
        : "r"(a[0]), "r"(a[1]), "r"(a[2]), "r"(a[3]), "r"(b0), "r"(b1));
}

// ======================= LPT order: rank batches by n_tiles desc ===========
__global__ void sort_kernel(const int* __restrict__ lens) {
    __shared__ int nts[B_];
    const int b = threadIdx.x;
    const int nt = (lens[b] + 127) >> 7;
    nts[b] = nt;
    __syncthreads();
    int rank = 0;
    for (int i = 0; i < B_; i++) {
        int o = nts[i];
        if (o > nt || (o == nt && i < b)) rank++;
    }
    g_perm[rank] = b;
}

// ============ prep: H -> bf16 hi/lo split AND hW = H.W (warp per row) ======
__global__ __launch_bounds__(256) void prep_h_kernel(const float* __restrict__ H,
                                                     const float* __restrict__ W,
                                                     const int* __restrict__ lens) {
    __shared__ float sW[D_];
    for (int d = threadIdx.x; d < D_; d += 256) sW[d] = W[d];
    __syncthreads();

    const int wid = threadIdx.x >> 5, lane = threadIdx.x & 31;
    const size_t row = (size_t)blockIdx.x * 8 + wid;
    const int t = (int)(row & (T_ - 1));
    const int b = (int)(row >> 9);
    if (t >= lens[b]) return;                 // whole warp exits together

    const float* src = H + row * D_;
    float s = 0.f;
    for (int d4 = lane; d4 < D_ / 4; d4 += 32) {
        float4 x = ((const float4*)src)[d4];
        __nv_bfloat16 h[4], l[4];
        h[0] = __float2bfloat16_rn(x.x); l[0] = __float2bfloat16_rn(x.x - __bfloat162float(h[0]));
        h[1] = __float2bfloat16_rn(x.y); l[1] = __float2bfloat16_rn(x.y - __bfloat162float(h[1]));
        h[2] = __float2bfloat16_rn(x.z); l[2] = __float2bfloat16_rn(x.z - __bfloat162float(h[2]));
        h[3] = __float2bfloat16_rn(x.w); l[3] = __float2bfloat16_rn(x.w - __bfloat162float(h[3]));
        *(uint2*)(g_Hhi + row * DP_ + d4 * 4) = *(const uint2*)h;
        *(uint2*)(g_Hlo + row * DP_ + d4 * 4) = *(const uint2*)l;
        const float* w = sW + d4 * 4;
        s += x.x * w[0] + x.y * w[1] + x.z * w[2] + x.w * w[3];
    }
#pragma unroll
    for (int o = 16; o; o >>= 1) s += __shfl_xor_sync(0xffffffffu, s, o);
    if (lane == 0) g_hW[row] = s;
}

// ======================= V: bf16 hi/lo split (warp per row) ================
__global__ __launch_bounds__(256) void split_v_kernel(const float* __restrict__ src) {
    const int wid = threadIdx.x >> 5, lane = threadIdx.x & 31;
    const size_t v = (size_t)blockIdx.x * 8 + wid;
    const float* s = src + v * D_;
    for (int d4 = lane; d4 < D_ / 4; d4 += 32) {
        float4 x = ((const float4*)s)[d4];
        __nv_bfloat16 h[4], l[4];
        h[0] = __float2bfloat16_rn(x.x); l[0] = __float2bfloat16_rn(x.x - __bfloat162float(h[0]));
        h[1] = __float2bfloat16_rn(x.y); l[1] = __float2bfloat16_rn(x.y - __bfloat162float(h[1]));
        h[2] = __float2bfloat16_rn(x.z); l[2] = __float2bfloat16_rn(x.z - __bfloat162float(h[2]));
        h[3] = __float2bfloat16_rn(x.w); l[3] = __float2bfloat16_rn(x.w - __bfloat162float(h[3]));
        *(uint2*)(g_Vhi + v * DP_ + d4 * 4) = *(const uint2*)h;
        *(uint2*)(g_Vlo + v * DP_ + d4 * 4) = *(const uint2*)l;
    }
}

// ======================= fused scores GEMM + softmax =======================
// R14 body (proven); batch selected through LPT permutation.
__global__ __launch_bounds__(256, 2) void fused_kernel(const int* __restrict__ lens,
                                                       const float* __restrict__ b_score,
                                                       float* __restrict__ y_utts) {
    extern __shared__ float sm[];
    float* hs = sm + NSTAGE * STAGE_WORDS;               // 512
    float4* part = (float4*)(hs + 512);                  // 256 float4
    float4* run  = part + 256;                           // 128 float4
    const uint32_t sbase = smem_u32(sm);

    const int tid = threadIdx.x, lane = tid & 31, wid = tid >> 5;
    const int g = lane >> 2, tig = lane & 3;
    const int warpM = wid & 3, warpN = wid >> 2;
    const int b = g_perm[blockIdx.y], v0 = blockIdx.x * 128;
    const int len_b = lens[b];
    const float bsc = b_score[0];
    const int n_tiles = (len_b + 127) >> 7;
    const int total_c = n_tiles * NCHUNK;

    for (int i = tid; i < T_; i += 256) hs[i] = g_hW[b * T_ + i];
    if (tid < 128) run[tid] = make_float4(-CUDART_INF_F, 0.f, 0.f, 0.f);
    __syncthreads();

    // ---- per-thread copy sources: 2 threads/row, each covers 16 elems ----
    const int crow = tid >> 1, ch = tid & 1;
    const __nv_bfloat16* pAh = g_Vhi + (size_t)(v0 + crow) * DP_ + ch * 16;
    const __nv_bfloat16* pAl = g_Vlo + (size_t)(v0 + crow) * DP_ + ch * 16;
    const __nv_bfloat16* pBh = g_Hhi + (size_t)(b * T_ + crow) * DP_ + ch * 16;
    const __nv_bfloat16* pBl = g_Hlo + (size_t)(b * T_ + crow) * DP_ + ch * 16;
    const uint32_t dst0 = sbase + (crow * STRIDEW + ch * 8) * 4;

    int cp_t = 0, cp_k = 0;
#define COPY_NEXT(ST) do {                                                     \
        uint32_t _d = dst0 + (ST) * STAGE_BYTES;                               \
        size_t _o = (size_t)cp_t * DP_ + cp_k;                                 \
        CP_ASYNC16(_d,                          pAh + cp_k);                   \
        CP_ASYNC16(_d + 16,                     pAh + cp_k + 8);               \
        CP_ASYNC16(_d + REG_WORDS * 4,          pAl + cp_k);                   \
        CP_ASYNC16(_d + REG_WORDS * 4 + 16,     pAl + cp_k + 8);               \
        CP_ASYNC16(_d + 2 * REG_WORDS * 4,      pBh + _o);                     \
        CP_ASYNC16(_d + 2 * REG_WORDS * 4 + 16, pBh + _o + 8);                 \
        CP_ASYNC16(_d + 3 * REG_WORDS * 4,      pBl + _o);                     \
        CP_ASYNC16(_d + 3 * REG_WORDS * 4 + 16, pBl + _o + 8);                 \
        cp_k += KC; if (cp_k == DP_) { cp_k = 0; cp_t += 128; }                \
    } while (0)

    // ---- ldmatrix per-thread offsets ----
    const int arow = lane & 15;
    const int acol = (lane >> 4) * 4;
    uint32_t aoff[2];
#pragma unroll
    for (int mt = 0; mt < 2; mt++)
        aoff[mt] = sbase + ((warpM * 32 + mt * 16 + arow) * STRIDEW + acol) * 4;
    const int brow = (lane & 7) + ((lane >> 4) & 1) * 8;
    const int bcol = ((lane >> 3) & 1) * 4;
    uint32_t boff[4];
#pragma unroll
    for (int p = 0; p < 4; p++)
        boff[p] = sbase + ((warpN * 64 + p * 16 + brow) * STRIDEW + bcol) * 4;

    COPY_NEXT(0); CP_COMMIT();

    int fc = 0;
    for (int tt = 0; tt < n_tiles; tt++) {
        const int t0 = tt * 128;

        float acc[2][8][4];
#pragma unroll
        for (int mt = 0; mt < 2; mt++)
#pragma unroll
            for (int nt = 0; nt < 8; nt++)
#pragma unroll
                for (int r = 0; r < 4; r++) acc[mt][nt][r] = 0.f;

        for (int kc = 0; kc < NCHUNK; kc++, fc++) {
            CP_WAIT0();                       // chunk fc landed (this thread)
            __syncthreads();                  // all threads' chunk fc visible

            const uint32_t so = (fc & 1) * STAGE_BYTES;
            const int do_copy = (fc + 1 < total_c);
#pragma unroll
            for (int s = 0; s < 2; s++) {
                const uint32_t so2 = so + s * 32;     // +8 words per k-step
                uint32_t ah[2][4], al[2][4], bb[4][4];
#pragma unroll
                for (int mt = 0; mt < 2; mt++) {
                    LDSM_X4(ah[mt], aoff[mt] + so2);
                    LDSM_X4(al[mt], aoff[mt] + so2 + REG_WORDS * 4);
                }
#pragma unroll
                for (int p = 0; p < 4; p++)
                    LDSM_X4(bb[p], boff[p] + so2 + 2 * REG_WORDS * 4);
                // ---- pass 1: hi*hi ----
#pragma unroll
                for (int nt = 0; nt < 8; nt++) {
                    const uint32_t b0 = bb[nt >> 1][(nt & 1) * 2];
                    const uint32_t b1 = bb[nt >> 1][(nt & 1) * 2 + 1];
#pragma unroll
                    for (int mt = 0; mt < 2; mt++)
                        mma16(acc[mt][nt], ah[mt], b0, b1);
                }
                // ---- copy next chunk (only once, after s=0 pass 1):
                // LSU issue hides under tensor drain of pass 1.
                if (s == 0) {
                    if (do_copy) COPY_NEXT((fc + 1) & 1);
                    CP_COMMIT();
                }
                // ---- pass 2: lo*hi ----
#pragma unroll
                for (int nt = 0; nt < 8; nt++) {
                    const uint32_t b0 = bb[nt >> 1][(nt & 1) * 2];
                    const uint32_t b1 = bb[nt >> 1][(nt & 1) * 2 + 1];
#pragma unroll
                    for (int mt = 0; mt < 2; mt++)
                        mma16(acc[mt][nt], al[mt], b0, b1);
                }
                // ---- pass 3: hi*lo ----
#pragma unroll
                for (int p = 0; p < 4; p++)
                    LDSM_X4(bb[p], boff[p] + so2 + 3 * REG_WORDS * 4);
#pragma unroll
                for (int nt = 0; nt < 8; nt++) {
                    const uint32_t b0 = bb[nt >> 1][(nt & 1) * 2];
                    const uint32_t b1 = bb[nt >> 1][(nt & 1) * 2 + 1];
#pragma unroll
                    for (int mt = 0; mt < 2; mt++)
                        mma16(acc[mt][nt], ah[mt], b0, b1);
                }
            }
        }

        // ---- epilogue: masked softmax partials ----
#pragma unroll
        for (int mt = 0; mt < 2; mt++)
#pragma unroll
            for (int rh = 0; rh < 2; rh++) {
                float m = -CUDART_INF_F;
#pragma unroll
                for (int nt = 0; nt < 8; nt++)
#pragma unroll
                    for (int j2 = 0; j2 < 2; j2++) {
                        int tc = t0 + warpN * 64 + nt * 8 + 2 * tig + j2;
                        float x = acc[mt][nt][rh * 2 + j2];
                        m = fmaxf(m, tc < len_b ? x : -CUDART_INF_F);
                    }
                m = fmaxf(m, __shfl_xor_sync(0xffffffffu, m, 1));
                m = fmaxf(m, __shfl_xor_sync(0xffffffffu, m, 2));
                float l = 0.f, w = 0.f;
#pragma unroll
                for (int nt = 0; nt < 8; nt++)
#pragma unroll
                    for (int j2 = 0; j2 < 2; j2++) {
                        int tc = t0 + warpN * 64 + nt * 8 + 2 * tig + j2;
                        if (tc < len_b) {
                            float e = __expf(acc[mt][nt][rh * 2 + j2] - m);
                            l += e;
                            w += e * hs[tc];
                        }
                    }
                l += __shfl_xor_sync(0xffffffffu, l, 1);
                l += __shfl_xor_sync(0xffffffffu, l, 2);
                w += __shfl_xor_sync(0xffffffffu, w, 1);
                w += __shfl_xor_sync(0xffffffffu, w, 2);
                if (tig == 0) {
                    int row = warpM * 32 + mt * 16 + g + rh * 8;
                    part[row * 2 + warpN] = make_float4(m, l, w, 0.f);
                }
            }
        __syncthreads();
        if (tid < 128) {
            float4 r = run[tid];
            float4 p0 = part[tid * 2 + 0];
            float4 p1 = part[tid * 2 + 1];
            float nm = fmaxf(r.x, fmaxf(p0.x, p1.x));
            float er = __expf(r.x - nm);
            float e0 = __expf(p0.x - nm);
            float e1 = __expf(p1.x - nm);
            r.y = r.y * er + p0.y * e0 + p1.y * e1;
            r.z = r.z * er + p0.z * e0 + p1.z * e1;
            r.x = nm;
            run[tid] = r;
        }
        // no trailing barrier: part is rewritten only after the next tile's
        // k-loop (13 chunk barriers in between); run is per-thread private.
    }

    if (tid < 128)
        y_utts[b * V_ + v0 + tid] = run[tid].z / run[tid].y + bsc;
#undef COPY_NEXT
}

// ======================= acts: s2 dot (warp per (b,a)) =====================
__global__ __launch_bounds__(256) void acts_s2_kernel(const float* __restrict__ C_acts,
                                                      const float* __restrict__ c_utt) {
    const int gw = blockIdx.x * 8 + (threadIdx.x >> 5);
    const int lane = threadIdx.x & 31;
    const int b = gw >> 7, a = gw & 127;
    const float4* cr = (const float4*)(C_acts + ((size_t)b * A_ + a) * D_);
    const float4* cu = (const float4*)(c_utt + (size_t)b * D_);
    float s = 0.f;
    for (int i = lane; i < D_ / 4; i += 32) {
        float4 x = cr[i], y = cu[i];
        s += x.x * y.x + x.y * y.y + x.z * y.z + x.w * y.w;
    }
#pragma unroll
    for (int o = 16; o; o >>= 1) s += __shfl_xor_sync(0xffffffffu, s, o);
    if (lane == 0) g_p[gw] = s;
}

// ======================= acts: softmax over a ==============================
__global__ __launch_bounds__(128) void acts_softmax_kernel() {
    __shared__ float w4[4], w4b[4];
    const int b = blockIdx.x;
    const int tid = threadIdx.x;
    const int warp = tid >> 5, lane = tid & 31;
    float s = g_p[b * A_ + tid];
    float m = s;
#pragma unroll
    for (int o = 16; o; o >>= 1) m = fmaxf(m, __shfl_xor_sync(0xffffffffu, m, o));
    if (lane == 0) w4[warp] = m;
    __syncthreads();
    m = fmaxf(fmaxf(w4[0], w4[1]), fmaxf(w4[2], w4[3]));
    float e = __expf(s - m);
    float smv = e;
#pragma unroll
    for (int o = 16; o; o >>= 1) smv += __shfl_xor_sync(0xffffffffu, smv, o);
    if (lane == 0) w4b[warp] = smv;
    __syncthreads();
    float tot = w4b[0] + w4b[1] + w4b[2] + w4b[3];
    g_p[b * A_ + tid] = e / tot;
}

// ======================= acts phase B: q = p @ C_acts ======================
__global__ __launch_bounds__(128) void acts_q_kernel(const float* __restrict__ C_acts) {
    __shared__ float p[A_];
    const int b = blockIdx.y;
    const int d = blockIdx.x * 100 + threadIdx.x;
    if (threadIdx.x < A_) p[threadIdx.x] = g_p[b * A_ + threadIdx.x];
    __syncthreads();
    if (threadIdx.x >= 100) return;
    const float* Cb = C_acts + (size_t)b * A_ * D_ + d;
    float q = 0.f;
#pragma unroll 4
    for (int a = 0; a < A_; a++) q = fmaf(p[a], Cb[(size_t)a * D_], q);
    g_q[b * D_ + d] = q;
}

// ======================= y_acts: warp per v-row ============================
__global__ __launch_bounds__(256) void yacts_kernel(const float* __restrict__ vals,
                                                    float* __restrict__ y_acts) {
    __shared__ float qs[16 * D_];
    const int tid = threadIdx.x, lane = tid & 31, wid = tid >> 5;
    const int b0 = blockIdx.y * 16;
    const int v = blockIdx.x * 8 + wid;

    for (int f = tid; f < 16 * D_; f += 256) qs[f] = g_q[b0 * D_ + f];
    __syncthreads();

    float acc[16];
#pragma unroll
    for (int bb = 0; bb < 16; bb++) acc[bb] = 0.f;

    const float4* vr = (const float4*)(vals + (size_t)v * D_);
    const float4* q4 = (const float4*)qs;
    for (int d4 = lane; d4 < D_ / 4; d4 += 32) {
        float4 r = vr[d4];
#pragma unroll
        for (int bb = 0; bb < 16; bb++) {
            float4 q = q4[bb * (D_ / 4) + d4];
            acc[bb] += r.x * q.x + r.y * q.y + r.z * q.z + r.w * q.w;
        }
    }
#pragma unroll
    for (int o = 16; o; o >>= 1)
#pragma unroll
        for (int bb = 0; bb < 16; bb++)
            acc[bb] += __shfl_xor_sync(0xffffffffu, acc[bb], o);
    if (lane == 0) {
#pragma unroll
        for (int bb = 0; bb < 16; bb++)
            y_acts[(size_t)(b0 + bb) * V_ + v] = acc[bb];
    }
}

// ===========================================================================
extern "C" void kernel_launch(void* const* d_in, const int* in_sizes, int n_in,
                              void* d_out, int out_size) {
    const float* H       = (const float*)d_in[0];
    const float* c_utt   = (const float*)d_in[1];
    const float* C_acts  = (const float*)d_in[2];
    const float* C_vals  = (const float*)d_in[3];
    const float* W       = (const float*)d_in[4];
    const float* b_score = (const float*)d_in[5];
    const int*   lens    = (const int*)d_in[6];

    float* y_utts = (float*)d_out;
    float* y_acts = (float*)d_out + (size_t)B_ * V_;

    static cudaStream_t s_side = nullptr, s_v = nullptr;
    static cudaEvent_t ev_fork = nullptr, ev_v = nullptr, ev_join = nullptr;
    if (!s_side) {
        cudaStreamCreateWithFlags(&s_side, cudaStreamNonBlocking);
        cudaStreamCreateWithFlags(&s_v, cudaStreamNonBlocking);
        cudaEventCreateWithFlags(&ev_fork, cudaEventDisableTiming);
        cudaEventCreateWithFlags(&ev_v, cudaEventDisableTiming);
        cudaEventCreateWithFlags(&ev_join, cudaEventDisableTiming);
        cudaFuncSetAttribute(fused_kernel,
                             cudaFuncAttributeMaxDynamicSharedMemorySize, SMEM_BYTES);
    }

    cudaEventRecord(ev_fork, 0);
    cudaStreamWaitEvent(s_side, ev_fork, 0);
    cudaStreamWaitEvent(s_v, ev_fork, 0);

    // V split overlaps sort+prep
    split_v_kernel<<<V_ / 8, 256, 0, s_v>>>(C_vals);
    cudaEventRecord(ev_v, s_v);

    sort_kernel<<<1, B_>>>(lens);
    prep_h_kernel<<<(B_ * T_) / 8, 256>>>(H, W, lens);
    cudaStreamWaitEvent(0, ev_v, 0);
    fused_kernel<<<dim3(V_ / 128, B_), 256, SMEM_BYTES>>>(lens, b_score, y_utts);

    // acts chain on side stream (independent)
    acts_s2_kernel<<<B_ * A_ / 8, 256, 0, s_side>>>(C_acts, c_utt);
    acts_softmax_kernel<<<B_, 128, 0, s_side>>>();
    acts_q_kernel<<<dim3(4, B_), 128, 0, s_side>>>(C_acts);
    yacts_kernel<<<dim3(V_ / 8, B_ / 16), 256, 0, s_side>>>(C_vals, y_acts);

    // join
    cudaEventRecord(ev_join, s_side);
    cudaStreamWaitEvent(0, ev_join, 0);
}

// round 16
// speedup vs baseline: 1.2174x; 1.0118x over previous
#include <cuda_runtime.h>
#include <cuda_bf16.h>
#include <math_constants.h>
#include <stdint.h>

#define B_ 128
#define T_ 512
#define D_ 400
#define DP_ 416                 // padded K (pad is zero-initialized, never written)
#define V_ 1024
#define A_ 128

#define KC      32              // K elems per chunk (two m16n8k16 steps)
#define NCHUNK  13              // 13*32 = 416
#define STRIDEW 20              // words per row (16 data + 4 pad), conflict-free
#define REG_WORDS   (128 * STRIDEW)
#define STAGE_WORDS (4 * REG_WORDS)     // Ahi, Alo, Bhi, Blo
#define STAGE_BYTES (STAGE_WORDS * 4)   // 40960
#define NSTAGE 2
#define SMEM_WORDS  (NSTAGE * STAGE_WORDS + 512 + 1024 + 512)
#define SMEM_BYTES  (SMEM_WORDS * 4)    // 90112

#define HB_ (B_ / 2)            // 64 batches per pipeline half

// -------- scratch (device globals; zero-initialized at load) ---------------
__device__ __align__(256) __nv_bfloat16 g_Hhi[B_ * T_ * DP_];
__device__ __align__(256) __nv_bfloat16 g_Hlo[B_ * T_ * DP_];
__device__ __align__(256) __nv_bfloat16 g_Vhi[V_ * DP_];
__device__ __align__(256) __nv_bfloat16 g_Vlo[V_ * DP_];
__device__ float g_hW[B_ * T_];
__device__ float g_p[B_ * A_];
__device__ float g_q[B_ * D_];
__device__ int   g_perm[B_];

// ======================= helpers ===========================================
__device__ __forceinline__ uint32_t smem_u32(const void* p) {
    uint32_t a;
    asm("{ .reg .u64 t; cvta.to.shared.u64 t, %1; cvt.u32.u64 %0, t; }"
        : "=r"(a) : "l"(p));
    return a;
}
#define CP_ASYNC16(dst, src) \
    asm volatile("cp.async.cg.shared.global [%0], [%1], 16;" \
                 :: "r"(dst), "l"(src) : "memory")
#define CP_COMMIT() asm volatile("cp.async.commit_group;" ::: "memory")
#define CP_WAIT0()  asm volatile("cp.async.wait_group 0;" ::: "memory")

#define LDSM_X4(R, addr)                                                      \
    asm volatile("ldmatrix.sync.aligned.m8n8.x4.shared.b16 {%0,%1,%2,%3}, [%4];" \
        : "=r"((R)[0]), "=r"((R)[1]), "=r"((R)[2]), "=r"((R)[3]) : "r"(addr))

__device__ __forceinline__ void mma16(float d[4], const uint32_t a[4],
                                      const uint32_t b0, const uint32_t b1) {
    asm volatile(
        "mma.sync.aligned.m16n8k16.row.col.f32.bf16.bf16.f32 "
        "{%0,%1,%2,%3}, {%4,%5,%6,%7}, {%8,%9}, {%0,%1,%2,%3};"
        : "+f"(d[0]), "+f"(d[1]), "+f"(d[2]), "+f"(d[3])
        : "r"(a[0]), "r"(a[1]), "r"(a[2]), "r"(a[3]), "r"(b0), "r"(b1));
}

// ======================= LPT order: rank batches by n_tiles desc ===========
__global__ void sort_kernel(const int* __restrict__ lens) {
    __shared__ int nts[B_];
    const int b = threadIdx.x;
    const int nt = (lens[b] + 127) >> 7;
    nts[b] = nt;
    __syncthreads();
    int rank = 0;
    for (int i = 0; i < B_; i++) {
        int o = nts[i];
        if (o > nt || (o == nt && i < b)) rank++;
    }
    g_perm[rank] = b;
}

// ============ prep: H -> bf16 hi/lo split AND hW = H.W (warp per row) ======
// Processes LPT ranks [rank_base, rank_base + HB_); batch via g_perm.
__global__ __launch_bounds__(256) void prep_h_kernel(const float* __restrict__ H,
                                                     const float* __restrict__ W,
                                                     const int* __restrict__ lens,
                                                     int rank_base) {
    __shared__ float sW[D_];
    for (int d = threadIdx.x; d < D_; d += 256) sW[d] = W[d];
    __syncthreads();

    const int wid = threadIdx.x >> 5, lane = threadIdx.x & 31;
    const int local = blockIdx.x * 8 + wid;           // [0, HB_*T_)
    const int b = g_perm[rank_base + (local >> 9)];
    const int t = local & (T_ - 1);
    if (t >= lens[b]) return;                 // whole warp exits together
    const size_t row = (size_t)b * T_ + t;

    const float* src = H + row * D_;
    float s = 0.f;
    for (int d4 = lane; d4 < D_ / 4; d4 += 32) {
        float4 x = ((const float4*)src)[d4];
        __nv_bfloat16 h[4], l[4];
        h[0] = __float2bfloat16_rn(x.x); l[0] = __float2bfloat16_rn(x.x - __bfloat162float(h[0]));
        h[1] = __float2bfloat16_rn(x.y); l[1] = __float2bfloat16_rn(x.y - __bfloat162float(h[1]));
        h[2] = __float2bfloat16_rn(x.z); l[2] = __float2bfloat16_rn(x.z - __bfloat162float(h[2]));
        h[3] = __float2bfloat16_rn(x.w); l[3] = __float2bfloat16_rn(x.w - __bfloat162float(h[3]));
        *(uint2*)(g_Hhi + row * DP_ + d4 * 4) = *(const uint2*)h;
        *(uint2*)(g_Hlo + row * DP_ + d4 * 4) = *(const uint2*)l;
        const float* w = sW + d4 * 4;
        s += x.x * w[0] + x.y * w[1] + x.z * w[2] + x.w * w[3];
    }
#pragma unroll
    for (int o = 16; o; o >>= 1) s += __shfl_xor_sync(0xffffffffu, s, o);
    if (lane == 0) g_hW[row] = s;
}

// ======================= V: bf16 hi/lo split (warp per row) ================
__global__ __launch_bounds__(256) void split_v_kernel(const float* __restrict__ src) {
    const int wid = threadIdx.x >> 5, lane = threadIdx.x & 31;
    const size_t v = (size_t)blockIdx.x * 8 + wid;
    const float* s = src + v * D_;
    for (int d4 = lane; d4 < D_ / 4; d4 += 32) {
        float4 x = ((const float4*)s)[d4];
        __nv_bfloat16 h[4], l[4];
        h[0] = __float2bfloat16_rn(x.x); l[0] = __float2bfloat16_rn(x.x - __bfloat162float(h[0]));
        h[1] = __float2bfloat16_rn(x.y); l[1] = __float2bfloat16_rn(x.y - __bfloat162float(h[1]));
        h[2] = __float2bfloat16_rn(x.z); l[2] = __float2bfloat16_rn(x.z - __bfloat162float(h[2]));
        h[3] = __float2bfloat16_rn(x.w); l[3] = __float2bfloat16_rn(x.w - __bfloat162float(h[3]));
        *(uint2*)(g_Vhi + v * DP_ + d4 * 4) = *(const uint2*)h;
        *(uint2*)(g_Vlo + v * DP_ + d4 * 4) = *(const uint2*)l;
    }
}

// ======================= fused scores GEMM + softmax =======================
// R14/R15 body (proven); batch = g_perm[rank_base + blockIdx.y].
__global__ __launch_bounds__(256, 2) void fused_kernel(const int* __restrict__ lens,
                                                       const float* __restrict__ b_score,
                                                       float* __restrict__ y_utts,
                                                       int rank_base) {
    extern __shared__ float sm[];
    float* hs = sm + NSTAGE * STAGE_WORDS;               // 512
    float4* part = (float4*)(hs + 512);                  // 256 float4
    float4* run  = part + 256;                           // 128 float4
    const uint32_t sbase = smem_u32(sm);

    const int tid = threadIdx.x, lane = tid & 31, wid = tid >> 5;
    const int g = lane >> 2, tig = lane & 3;
    const int warpM = wid & 3, warpN = wid >> 2;
    const int b = g_perm[rank_base + blockIdx.y], v0 = blockIdx.x * 128;
    const int len_b = lens[b];
    const float bsc = b_score[0];
    const int n_tiles = (len_b + 127) >> 7;
    const int total_c = n_tiles * NCHUNK;

    for (int i = tid; i < T_; i += 256) hs[i] = g_hW[b * T_ + i];
    if (tid < 128) run[tid] = make_float4(-CUDART_INF_F, 0.f, 0.f, 0.f);
    __syncthreads();

    // ---- per-thread copy sources: 2 threads/row, each covers 16 elems ----
    const int crow = tid >> 1, ch = tid & 1;
    const __nv_bfloat16* pAh = g_Vhi + (size_t)(v0 + crow) * DP_ + ch * 16;
    const __nv_bfloat16* pAl = g_Vlo + (size_t)(v0 + crow) * DP_ + ch * 16;
    const __nv_bfloat16* pBh = g_Hhi + (size_t)(b * T_ + crow) * DP_ + ch * 16;
    const __nv_bfloat16* pBl = g_Hlo + (size_t)(b * T_ + crow) * DP_ + ch * 16;
    const uint32_t dst0 = sbase + (crow * STRIDEW + ch * 8) * 4;

    int cp_t = 0, cp_k = 0;
#define COPY_NEXT(ST) do {                                                     \
        uint32_t _d = dst0 + (ST) * STAGE_BYTES;                               \
        size_t _o = (size_t)cp_t * DP_ + cp_k;                                 \
        CP_ASYNC16(_d,                          pAh + cp_k);                   \
        CP_ASYNC16(_d + 16,                     pAh + cp_k + 8);               \
        CP_ASYNC16(_d + REG_WORDS * 4,          pAl + cp_k);                   \
        CP_ASYNC16(_d + REG_WORDS * 4 + 16,     pAl + cp_k + 8);               \
        CP_ASYNC16(_d + 2 * REG_WORDS * 4,      pBh + _o);                     \
        CP_ASYNC16(_d + 2 * REG_WORDS * 4 + 16, pBh + _o + 8);                 \
        CP_ASYNC16(_d + 3 * REG_WORDS * 4,      pBl + _o);                     \
        CP_ASYNC16(_d + 3 * REG_WORDS * 4 + 16, pBl + _o + 8);                 \
        cp_k += KC; if (cp_k == DP_) { cp_k = 0; cp_t += 128; }                \
    } while (0)

    // ---- ldmatrix per-thread offsets ----
    const int arow = lane & 15;
    const int acol = (lane >> 4) * 4;
    uint32_t aoff[2];
#pragma unroll
    for (int mt = 0; mt < 2; mt++)
        aoff[mt] = sbase + ((warpM * 32 + mt * 16 + arow) * STRIDEW + acol) * 4;
    const int brow = (lane & 7) + ((lane >> 4) & 1) * 8;
    const int bcol = ((lane >> 3) & 1) * 4;
    uint32_t boff[4];
#pragma unroll
    for (int p = 0; p < 4; p++)
        boff[p] = sbase + ((warpN * 64 + p * 16 + brow) * STRIDEW + bcol) * 4;

    COPY_NEXT(0); CP_COMMIT();

    int fc = 0;
    for (int tt = 0; tt < n_tiles; tt++) {
        const int t0 = tt * 128;

        float acc[2][8][4];
#pragma unroll
        for (int mt = 0; mt < 2; mt++)
#pragma unroll
            for (int nt = 0; nt < 8; nt++)
#pragma unroll
                for (int r = 0; r < 4; r++) acc[mt][nt][r] = 0.f;

        for (int kc = 0; kc < NCHUNK; kc++, fc++) {
            CP_WAIT0();                       // chunk fc landed (this thread)
            __syncthreads();                  // all threads' chunk fc visible

            const uint32_t so = (fc & 1) * STAGE_BYTES;
            const int do_copy = (fc + 1 < total_c);
#pragma unroll
            for (int s = 0; s < 2; s++) {
                const uint32_t so2 = so + s * 32;     // +8 words per k-step
                uint32_t ah[2][4], al[2][4], bb[4][4];
#pragma unroll
                for (int mt = 0; mt < 2; mt++) {
                    LDSM_X4(ah[mt], aoff[mt] + so2);
                    LDSM_X4(al[mt], aoff[mt] + so2 + REG_WORDS * 4);
                }
#pragma unroll
                for (int p = 0; p < 4; p++)
                    LDSM_X4(bb[p], boff[p] + so2 + 2 * REG_WORDS * 4);
                // ---- pass 1: hi*hi ----
#pragma unroll
                for (int nt = 0; nt < 8; nt++) {
                    const uint32_t b0 = bb[nt >> 1][(nt & 1) * 2];
                    const uint32_t b1 = bb[nt >> 1][(nt & 1) * 2 + 1];
#pragma unroll
                    for (int mt = 0; mt < 2; mt++)
                        mma16(acc[mt][nt], ah[mt], b0, b1);
                }
                // ---- copy next chunk (only once, after s=0 pass 1):
                // LSU issue hides under tensor drain of pass 1.
                if (s == 0) {
                    if (do_copy) COPY_NEXT((fc + 1) & 1);
                    CP_COMMIT();
                }
                // ---- pass 2: lo*hi ----
#pragma unroll
                for (int nt = 0; nt < 8; nt++) {
                    const uint32_t b0 = bb[nt >> 1][(nt & 1) * 2];
                    const uint32_t b1 = bb[nt >> 1][(nt & 1) * 2 + 1];
#pragma unroll
                    for (int mt = 0; mt < 2; mt++)
                        mma16(acc[mt][nt], al[mt], b0, b1);
                }
                // ---- pass 3: hi*lo ----
#pragma unroll
                for (int p = 0; p < 4; p++)
                    LDSM_X4(bb[p], boff[p] + so2 + 3 * REG_WORDS * 4);
#pragma unroll
                for (int nt = 0; nt < 8; nt++) {
                    const uint32_t b0 = bb[nt >> 1][(nt & 1) * 2];
                    const uint32_t b1 = bb[nt >> 1][(nt & 1) * 2 + 1];
#pragma unroll
                    for (int mt = 0; mt < 2; mt++)
                        mma16(acc[mt][nt], ah[mt], b0, b1);
                }
            }
        }

        // ---- epilogue: masked softmax partials ----
#pragma unroll
        for (int mt = 0; mt < 2; mt++)
#pragma unroll
            for (int rh = 0; rh < 2; rh++) {
                float m = -CUDART_INF_F;
#pragma unroll
                for (int nt = 0; nt < 8; nt++)
#pragma unroll
                    for (int j2 = 0; j2 < 2; j2++) {
                        int tc = t0 + warpN * 64 + nt * 8 + 2 * tig + j2;
                        float x = acc[mt][nt][rh * 2 + j2];
                        m = fmaxf(m, tc < len_b ? x : -CUDART_INF_F);
                    }
                m = fmaxf(m, __shfl_xor_sync(0xffffffffu, m, 1));
                m = fmaxf(m, __shfl_xor_sync(0xffffffffu, m, 2));
                float l = 0.f, w = 0.f;
#pragma unroll
                for (int nt = 0; nt < 8; nt++)
#pragma unroll
                    for (int j2 = 0; j2 < 2; j2++) {
                        int tc = t0 + warpN * 64 + nt * 8 + 2 * tig + j2;
                        if (tc < len_b) {
                            float e = __expf(acc[mt][nt][rh * 2 + j2] - m);
                            l += e;
                            w += e * hs[tc];
                        }
                    }
                l += __shfl_xor_sync(0xffffffffu, l, 1);
                l += __shfl_xor_sync(0xffffffffu, l, 2);
                w += __shfl_xor_sync(0xffffffffu, w, 1);
                w += __shfl_xor_sync(0xffffffffu, w, 2);
                if (tig == 0) {
                    int row = warpM * 32 + mt * 16 + g + rh * 8;
                    part[row * 2 + warpN] = make_float4(m, l, w, 0.f);
                }
            }
        __syncthreads();
        if (tid < 128) {
            float4 r = run[tid];
            float4 p0 = part[tid * 2 + 0];
            float4 p1 = part[tid * 2 + 1];
            float nm = fmaxf(r.x, fmaxf(p0.x, p1.x));
            float er = __expf(r.x - nm);
            float e0 = __expf(p0.x - nm);
            float e1 = __expf(p1.x - nm);
            r.y = r.y * er + p0.y * e0 + p1.y * e1;
            r.z = r.z * er + p0.z * e0 + p1.z * e1;
            r.x = nm;
            run[tid] = r;
        }
        // no trailing barrier: part is rewritten only after the next tile's
        // k-loop (13 chunk barriers in between); run is per-thread private.
    }

    if (tid < 128)
        y_utts[b * V_ + v0 + tid] = run[tid].z / run[tid].y + bsc;
#undef COPY_NEXT
}

// ======================= acts: s2 dot (warp per (b,a)) =====================
__global__ __launch_bounds__(256) void acts_s2_kernel(const float* __restrict__ C_acts,
                                                      const float* __restrict__ c_utt) {
    const int gw = blockIdx.x * 8 + (threadIdx.x >> 5);
    const int lane = threadIdx.x & 31;
    const int b = gw >> 7, a = gw & 127;
    const float4* cr = (const float4*)(C_acts + ((size_t)b * A_ + a) * D_);
    const float4* cu = (const float4*)(c_utt + (size_t)b * D_);
    float s = 0.f;
    for (int i = lane; i < D_ / 4; i += 32) {
        float4 x = cr[i], y = cu[i];
        s += x.x * y.x + x.y * y.y + x.z * y.z + x.w * y.w;
    }
#pragma unroll
    for (int o = 16; o; o >>= 1) s += __shfl_xor_sync(0xffffffffu, s, o);
    if (lane == 0) g_p[gw] = s;
}

// ======================= acts: softmax over a ==============================
__global__ __launch_bounds__(128) void acts_softmax_kernel() {
    __shared__ float w4[4], w4b[4];
    const int b = blockIdx.x;
    const int tid = threadIdx.x;
    const int warp = tid >> 5, lane = tid & 31;
    float s = g_p[b * A_ + tid];
    float m = s;
#pragma unroll
    for (int o = 16; o; o >>= 1) m = fmaxf(m, __shfl_xor_sync(0xffffffffu, m, o));
    if (lane == 0) w4[warp] = m;
    __syncthreads();
    m = fmaxf(fmaxf(w4[0], w4[1]), fmaxf(w4[2], w4[3]));
    float e = __expf(s - m);
    float smv = e;
#pragma unroll
    for (int o = 16; o; o >>= 1) smv += __shfl_xor_sync(0xffffffffu, smv, o);
    if (lane == 0) w4b[warp] = smv;
    __syncthreads();
    float tot = w4b[0] + w4b[1] + w4b[2] + w4b[3];
    g_p[b * A_ + tid] = e / tot;
}

// ======================= acts phase B: q = p @ C_acts ======================
__global__ __launch_bounds__(128) void acts_q_kernel(const float* __restrict__ C_acts) {
    __shared__ float p[A_];
    const int b = blockIdx.y;
    const int d = blockIdx.x * 100 + threadIdx.x;
    if (threadIdx.x < A_) p[threadIdx.x] = g_p[b * A_ + threadIdx.x];
    __syncthreads();
    if (threadIdx.x >= 100) return;
    const float* Cb = C_acts + (size_t)b * A_ * D_ + d;
    float q = 0.f;
#pragma unroll 4
    for (int a = 0; a < A_; a++) q = fmaf(p[a], Cb[(size_t)a * D_], q);
    g_q[b * D_ + d] = q;
}

// ======================= y_acts: warp per v-row ============================
__global__ __launch_bounds__(256) void yacts_kernel(const float* __restrict__ vals,
                                                    float* __restrict__ y_acts) {
    __shared__ float qs[16 * D_];
    const int tid = threadIdx.x, lane = tid & 31, wid = tid >> 5;
    const int b0 = blockIdx.y * 16;
    const int v = blockIdx.x * 8 + wid;

    for (int f = tid; f < 16 * D_; f += 256) qs[f] = g_q[b0 * D_ + f];
    __syncthreads();

    float acc[16];
#pragma unroll
    for (int bb = 0; bb < 16; bb++) acc[bb] = 0.f;

    const float4* vr = (const float4*)(vals + (size_t)v * D_);
    const float4* q4 = (const float4*)qs;
    for (int d4 = lane; d4 < D_ / 4; d4 += 32) {
        float4 r = vr[d4];
#pragma unroll
        for (int bb = 0; bb < 16; bb++) {
            float4 q = q4[bb * (D_ / 4) + d4];
            acc[bb] += r.x * q.x + r.y * q.y + r.z * q.z + r.w * q.w;
        }
    }
#pragma unroll
    for (int o = 16; o; o >>= 1)
#pragma unroll
        for (int bb = 0; bb < 16; bb++)
            acc[bb] += __shfl_xor_sync(0xffffffffu, acc[bb], o);
    if (lane == 0) {
#pragma unroll
        for (int bb = 0; bb < 16; bb++)
            y_acts[(size_t)(b0 + bb) * V_ + v] = acc[bb];
    }
}

// ===========================================================================
extern "C" void kernel_launch(void* const* d_in, const int* in_sizes, int n_in,
                              void* d_out, int out_size) {
    const float* H       = (const float*)d_in[0];
    const float* c_utt   = (const float*)d_in[1];
    const float* C_acts  = (const float*)d_in[2];
    const float* C_vals  = (const float*)d_in[3];
    const float* W       = (const float*)d_in[4];
    const float* b_score = (const float*)d_in[5];
    const int*   lens    = (const int*)d_in[6];

    float* y_utts = (float*)d_out;
    float* y_acts = (float*)d_out + (size_t)B_ * V_;

    static cudaStream_t sS = nullptr, sT = nullptr, sV = nullptr;
    static cudaEvent_t evFork = nullptr, evPrep1 = nullptr, evV = nullptr,
                       evS = nullptr, evT = nullptr;
    if (!sS) {
        cudaStreamCreateWithFlags(&sS, cudaStreamNonBlocking);
        cudaStreamCreateWithFlags(&sT, cudaStreamNonBlocking);
        cudaStreamCreateWithFlags(&sV, cudaStreamNonBlocking);
        cudaEventCreateWithFlags(&evFork, cudaEventDisableTiming);
        cudaEventCreateWithFlags(&evPrep1, cudaEventDisableTiming);
        cudaEventCreateWithFlags(&evV, cudaEventDisableTiming);
        cudaEventCreateWithFlags(&evS, cudaEventDisableTiming);
        cudaEventCreateWithFlags(&evT, cudaEventDisableTiming);
        cudaFuncSetAttribute(fused_kernel,
                             cudaFuncAttributeMaxDynamicSharedMemorySize, SMEM_BYTES);
    }

    cudaEventRecord(evFork, 0);
    cudaStreamWaitEvent(sT, evFork, 0);
    cudaStreamWaitEvent(sV, evFork, 0);

    // V split overlaps sort + prep1
    split_v_kernel<<<V_ / 8, 256, 0, sV>>>(C_vals);
    cudaEventRecord(evV, sV);

    // main: sort -> prep half 1 (LPT ranks 0..63) -> fused half 1
    sort_kernel<<<1, B_>>>(lens);
    prep_h_kernel<<<(HB_ * T_) / 8, 256>>>(H, W, lens, 0);
    cudaEventRecord(evPrep1, 0);
    cudaStreamWaitEvent(0, evV, 0);
    fused_kernel<<<dim3(V_ / 128, HB_), 256, SMEM_BYTES>>>(lens, b_score, y_utts, 0);

    // side S: prep half 2 overlaps fused1; fused half 2 backfills fused1 tail
    cudaStreamWaitEvent(sS, evPrep1, 0);
    cudaStreamWaitEvent(sS, evV, 0);
    prep_h_kernel<<<(HB_ * T_) / 8, 256, 0, sS>>>(H, W, lens, HB_);
    fused_kernel<<<dim3(V_ / 128, HB_), 256, SMEM_BYTES, sS>>>(lens, b_score, y_utts, HB_);
    cudaEventRecord(evS, sS);

    // acts chain on stream T (independent)
    acts_s2_kernel<<<B_ * A_ / 8, 256, 0, sT>>>(C_acts, c_utt);
    acts_softmax_kernel<<<B_, 128, 0, sT>>>();
    acts_q_kernel<<<dim3(4, B_), 128, 0, sT>>>(C_acts);
    yacts_kernel<<<dim3(V_ / 8, B_ / 16), 256, 0, sT>>>(C_vals, y_acts);
    cudaEventRecord(evT, sT);

    // join
    cudaStreamWaitEvent(0, evS, 0);
    cudaStreamWaitEvent(0, evT, 0);
}

// round 17
// speedup vs baseline: 1.2305x; 1.0108x over previous
#include <cuda_runtime.h>
#include <cuda_bf16.h>
#include <math_constants.h>
#include <stdint.h>

#define B_ 128
#define T_ 512
#define D_ 400
#define DP_ 416                 // padded K (pad is zero-initialized, never written)
#define V_ 1024
#define A_ 128

#define KC      32              // K elems per chunk (two m16n8k16 steps)
#define NCHUNK  13              // 13*32 = 416
#define STRIDEW 20              // words per row (16 data + 4 pad), conflict-free
#define REG_WORDS   (128 * STRIDEW)
#define STAGE_WORDS (4 * REG_WORDS)     // Ahi, Alo, Bhi, Blo
#define STAGE_BYTES (STAGE_WORDS * 4)   // 40960
#define NSTAGE 2
#define SMEM_WORDS  (NSTAGE * STAGE_WORDS + 128 + 1024)
#define SMEM_BYTES  (SMEM_WORDS * 4)    // 86528

#define HB_ (B_ / 2)            // 64 ranks per pipeline half
#define MAXI_HALF 2048          // worst-case items per half (64 * 4 * 8)

// -------- scratch (device globals; zero-initialized at load) ---------------
__device__ __align__(256) __nv_bfloat16 g_Hhi[B_ * T_ * DP_];
__device__ __align__(256) __nv_bfloat16 g_Hlo[B_ * T_ * DP_];
__device__ __align__(256) __nv_bfloat16 g_Vhi[V_ * DP_];
__device__ __align__(256) __nv_bfloat16 g_Vlo[V_ * DP_];
__device__ float g_hW[B_ * T_];
__device__ float g_p[B_ * A_];
__device__ float g_q[B_ * D_];
__device__ int   g_perm[B_];
__device__ int   g_items[2 * MAXI_HALF];
__device__ int   g_cnt1, g_total;
__device__ __align__(256) float4 g_tpart[B_ * 8 * 4 * 128];   // 8 MB partials

// ======================= helpers ===========================================
__device__ __forceinline__ uint32_t smem_u32(const void* p) {
    uint32_t a;
    asm("{ .reg .u64 t; cvta.to.shared.u64 t, %1; cvt.u32.u64 %0, t; }"
        : "=r"(a) : "l"(p));
    return a;
}
#define CP_ASYNC16(dst, src) \
    asm volatile("cp.async.cg.shared.global [%0], [%1], 16;" \
                 :: "r"(dst), "l"(src) : "memory")
#define CP_COMMIT() asm volatile("cp.async.commit_group;" ::: "memory")
#define CP_WAIT0()  asm volatile("cp.async.wait_group 0;" ::: "memory")

#define LDSM_X4(R, addr)                                                      \
    asm volatile("ldmatrix.sync.aligned.m8n8.x4.shared.b16 {%0,%1,%2,%3}, [%4];" \
        : "=r"((R)[0]), "=r"((R)[1]), "=r"((R)[2]), "=r"((R)[3]) : "r"(addr))

__device__ __forceinline__ void mma16(float d[4], const uint32_t a[4],
                                      const uint32_t b0, const uint32_t b1) {
    asm volatile(
        "mma.sync.aligned.m16n8k16.row.col.f32.bf16.bf16.f32 "
        "{%0,%1,%2,%3}, {%4,%5,%6,%7}, {%8,%9}, {%0,%1,%2,%3};"
        : "+f"(d[0]), "+f"(d[1]), "+f"(d[2]), "+f"(d[3])
        : "r"(a[0]), "r"(a[1]), "r"(a[2]), "r"(a[3]), "r"(b0), "r"(b1));
}

// ====== sort: LPT rank, build split-T item list + half boundaries ==========
__global__ void sort_kernel(const int* __restrict__ lens) {
    __shared__ int nts[B_];   // by batch
    __shared__ int prm[B_];   // rank -> batch
    __shared__ int ntr[B_];   // rank -> n_tiles
    const int b = threadIdx.x;
    const int nt = (lens[b] + 127) >> 7;
    nts[b] = nt;
    __syncthreads();
    int rank = 0;
    for (int i = 0; i < B_; i++) {
        int o = nts[i];
        if (o > nt || (o == nt && i < b)) rank++;
    }
    prm[rank] = b; ntr[rank] = nt;
    g_perm[rank] = b;
    __syncthreads();
    const int r = threadIdx.x;          // reinterpret tid as rank
    int pre = 0;
    for (int i = 0; i < r; i++) pre += ntr[i];
    const int bb = prm[r], ntt = ntr[r];
    const int base = 8 * pre;
    for (int tt = 0; tt < ntt; tt++)
        for (int v = 0; v < 8; v++)
            g_items[base + tt * 8 + v] = bb | (v << 7) | (tt << 10);
    if (r == HB_)    g_cnt1  = 8 * pre;
    if (r == B_ - 1) g_total = 8 * (pre + ntt);
}

// ============ prep: H -> bf16 hi/lo split AND hW = H.W (warp per row) ======
__global__ __launch_bounds__(256) void prep_h_kernel(const float* __restrict__ H,
                                                     const float* __restrict__ W,
                                                     const int* __restrict__ lens,
                                                     int rank_base) {
    __shared__ float sW[D_];
    for (int d = threadIdx.x; d < D_; d += 256) sW[d] = W[d];
    __syncthreads();

    const int wid = threadIdx.x >> 5, lane = threadIdx.x & 31;
    const int local = blockIdx.x * 8 + wid;
    const int b = g_perm[rank_base + (local >> 9)];
    const int t = local & (T_ - 1);
    if (t >= lens[b]) return;                 // whole warp exits together
    const size_t row = (size_t)b * T_ + t;

    const float* src = H + row * D_;
    float s = 0.f;
    for (int d4 = lane; d4 < D_ / 4; d4 += 32) {
        float4 x = ((const float4*)src)[d4];
        __nv_bfloat16 h[4], l[4];
        h[0] = __float2bfloat16_rn(x.x); l[0] = __float2bfloat16_rn(x.x - __bfloat162float(h[0]));
        h[1] = __float2bfloat16_rn(x.y); l[1] = __float2bfloat16_rn(x.y - __bfloat162float(h[1]));
        h[2] = __float2bfloat16_rn(x.z); l[2] = __float2bfloat16_rn(x.z - __bfloat162float(h[2]));
        h[3] = __float2bfloat16_rn(x.w); l[3] = __float2bfloat16_rn(x.w - __bfloat162float(h[3]));
        *(uint2*)(g_Hhi + row * DP_ + d4 * 4) = *(const uint2*)h;
        *(uint2*)(g_Hlo + row * DP_ + d4 * 4) = *(const uint2*)l;
        const float* w = sW + d4 * 4;
        s += x.x * w[0] + x.y * w[1] + x.z * w[2] + x.w * w[3];
    }
#pragma unroll
    for (int o = 16; o; o >>= 1) s += __shfl_xor_sync(0xffffffffu, s, o);
    if (lane == 0) g_hW[row] = s;
}

// ======================= V: bf16 hi/lo split (warp per row) ================
__global__ __launch_bounds__(256) void split_v_kernel(const float* __restrict__ src) {
    const int wid = threadIdx.x >> 5, lane = threadIdx.x & 31;
    const size_t v = (size_t)blockIdx.x * 8 + wid;
    const float* s = src + v * D_;
    for (int d4 = lane; d4 < D_ / 4; d4 += 32) {
        float4 x = ((const float4*)s)[d4];
        __nv_bfloat16 h[4], l[4];
        h[0] = __float2bfloat16_rn(x.x); l[0] = __float2bfloat16_rn(x.x - __bfloat162float(h[0]));
        h[1] = __float2bfloat16_rn(x.y); l[1] = __float2bfloat16_rn(x.y - __bfloat162float(h[1]));
        h[2] = __float2bfloat16_rn(x.z); l[2] = __float2bfloat16_rn(x.z - __bfloat162float(h[2]));
        h[3] = __float2bfloat16_rn(x.w); l[3] = __float2bfloat16_rn(x.w - __bfloat162float(h[3]));
        *(uint2*)(g_Vhi + v * DP_ + d4 * 4) = *(const uint2*)h;
        *(uint2*)(g_Vlo + v * DP_ + d4 * 4) = *(const uint2*)l;
    }
}

// ======================= fused: one (b, v-tile, t-tile) item per CTA =======
// R14 chunk body (proven); 13 chunks; writes per-tile softmax partial.
__global__ __launch_bounds__(256, 2) void fused_kernel(const int* __restrict__ lens,
                                                       int half) {
    extern __shared__ float sm[];
    float* hs = sm + NSTAGE * STAGE_WORDS;               // 128 floats
    float4* part = (float4*)(hs + 128);                  // 256 float4
    const uint32_t sbase = smem_u32(sm);

    const int idx = (half ? g_cnt1 : 0) + blockIdx.x;
    const int limit = half ? g_total : g_cnt1;
    if (idx >= limit) return;
    const int code = g_items[idx];
    const int b  = code & 127;
    const int vt = (code >> 7) & 7;
    const int tt = (code >> 10) & 3;
    const int v0 = vt * 128, t0 = tt * 128;
    const int len_b = lens[b];

    const int tid = threadIdx.x, lane = tid & 31, wid = tid >> 5;
    const int g = lane >> 2, tig = lane & 3;
    const int warpM = wid & 3, warpN = wid >> 2;

    if (tid < 128) hs[tid] = g_hW[b * T_ + t0 + tid];

    // ---- per-thread copy sources: 2 threads/row, each covers 16 elems ----
    const int crow = tid >> 1, ch = tid & 1;
    const __nv_bfloat16* pAh = g_Vhi + (size_t)(v0 + crow) * DP_ + ch * 16;
    const __nv_bfloat16* pAl = g_Vlo + (size_t)(v0 + crow) * DP_ + ch * 16;
    const __nv_bfloat16* pBh = g_Hhi + (size_t)(b * T_ + t0 + crow) * DP_ + ch * 16;
    const __nv_bfloat16* pBl = g_Hlo + (size_t)(b * T_ + t0 + crow) * DP_ + ch * 16;
    const uint32_t dst0 = sbase + (crow * STRIDEW + ch * 8) * 4;

    int cp_k = 0;
#define COPY_NEXT(ST) do {                                                     \
        uint32_t _d = dst0 + (ST) * STAGE_BYTES;                               \
        CP_ASYNC16(_d,                          pAh + cp_k);                   \
        CP_ASYNC16(_d + 16,                     pAh + cp_k + 8);               \
        CP_ASYNC16(_d + REG_WORDS * 4,          pAl + cp_k);                   \
        CP_ASYNC16(_d + REG_WORDS * 4 + 16,     pAl + cp_k + 8);               \
        CP_ASYNC16(_d + 2 * REG_WORDS * 4,      pBh + cp_k);                   \
        CP_ASYNC16(_d + 2 * REG_WORDS * 4 + 16, pBh + cp_k + 8);               \
        CP_ASYNC16(_d + 3 * REG_WORDS * 4,      pBl + cp_k);                   \
        CP_ASYNC16(_d + 3 * REG_WORDS * 4 + 16, pBl + cp_k + 8);               \
        cp_k += KC;                                                            \
    } while (0)

    // ---- ldmatrix per-thread offsets ----
    const int arow = lane & 15;
    const int acol = (lane >> 4) * 4;
    uint32_t aoff[2];
#pragma unroll
    for (int mt = 0; mt < 2; mt++)
        aoff[mt] = sbase + ((warpM * 32 + mt * 16 + arow) * STRIDEW + acol) * 4;
    const int brow = (lane & 7) + ((lane >> 4) & 1) * 8;
    const int bcol = ((lane >> 3) & 1) * 4;
    uint32_t boff[4];
#pragma unroll
    for (int p = 0; p < 4; p++)
        boff[p] = sbase + ((warpN * 64 + p * 16 + brow) * STRIDEW + bcol) * 4;

    COPY_NEXT(0); CP_COMMIT();

    float acc[2][8][4];
#pragma unroll
    for (int mt = 0; mt < 2; mt++)
#pragma unroll
        for (int nt = 0; nt < 8; nt++)
#pragma unroll
            for (int r = 0; r < 4; r++) acc[mt][nt][r] = 0.f;

    for (int fc = 0; fc < NCHUNK; fc++) {
        CP_WAIT0();                       // chunk fc landed (this thread)
        __syncthreads();                  // all threads' chunk fc visible

        const uint32_t so = (fc & 1) * STAGE_BYTES;
        const int do_copy = (fc + 1 < NCHUNK);
#pragma unroll
        for (int s = 0; s < 2; s++) {
            const uint32_t so2 = so + s * 32;     // +8 words per k-step
            uint32_t ah[2][4], al[2][4], bb[4][4];
#pragma unroll
            for (int mt = 0; mt < 2; mt++) {
                LDSM_X4(ah[mt], aoff[mt] + so2);
                LDSM_X4(al[mt], aoff[mt] + so2 + REG_WORDS * 4);
            }
#pragma unroll
            for (int p = 0; p < 4; p++)
                LDSM_X4(bb[p], boff[p] + so2 + 2 * REG_WORDS * 4);
            // ---- pass 1: hi*hi ----
#pragma unroll
            for (int nt = 0; nt < 8; nt++) {
                const uint32_t b0 = bb[nt >> 1][(nt & 1) * 2];
                const uint32_t b1 = bb[nt >> 1][(nt & 1) * 2 + 1];
#pragma unroll
                for (int mt = 0; mt < 2; mt++)
                    mma16(acc[mt][nt], ah[mt], b0, b1);
            }
            // ---- copy next chunk after pass 1 (hides under tensor drain) ----
            if (s == 0) {
                if (do_copy) COPY_NEXT((fc + 1) & 1);
                CP_COMMIT();
            }
            // ---- pass 2: lo*hi ----
#pragma unroll
            for (int nt = 0; nt < 8; nt++) {
                const uint32_t b0 = bb[nt >> 1][(nt & 1) * 2];
                const uint32_t b1 = bb[nt >> 1][(nt & 1) * 2 + 1];
#pragma unroll
                for (int mt = 0; mt < 2; mt++)
                    mma16(acc[mt][nt], al[mt], b0, b1);
            }
            // ---- pass 3: hi*lo ----
#pragma unroll
            for (int p = 0; p < 4; p++)
                LDSM_X4(bb[p], boff[p] + so2 + 3 * REG_WORDS * 4);
#pragma unroll
            for (int nt = 0; nt < 8; nt++) {
                const uint32_t b0 = bb[nt >> 1][(nt & 1) * 2];
                const uint32_t b1 = bb[nt >> 1][(nt & 1) * 2 + 1];
#pragma unroll
                for (int mt = 0; mt < 2; mt++)
                    mma16(acc[mt][nt], ah[mt], b0, b1);
            }
        }
    }

    // ---- epilogue: masked per-tile softmax partials ----
#pragma unroll
    for (int mt = 0; mt < 2; mt++)
#pragma unroll
        for (int rh = 0; rh < 2; rh++) {
            float m = -CUDART_INF_F;
#pragma unroll
            for (int nt = 0; nt < 8; nt++)
#pragma unroll
                for (int j2 = 0; j2 < 2; j2++) {
                    int tc = t0 + warpN * 64 + nt * 8 + 2 * tig + j2;
                    float x = acc[mt][nt][rh * 2 + j2];
                    m = fmaxf(m, tc < len_b ? x : -CUDART_INF_F);
                }
            m = fmaxf(m, __shfl_xor_sync(0xffffffffu, m, 1));
            m = fmaxf(m, __shfl_xor_sync(0xffffffffu, m, 2));
            float l = 0.f, w = 0.f;
#pragma unroll
            for (int nt = 0; nt < 8; nt++)
#pragma unroll
                for (int j2 = 0; j2 < 2; j2++) {
                    int tc = t0 + warpN * 64 + nt * 8 + 2 * tig + j2;
                    if (tc < len_b) {
                        float e = __expf(acc[mt][nt][rh * 2 + j2] - m);
                        l += e;
                        w += e * hs[warpN * 64 + nt * 8 + 2 * tig + j2];
                    }
                }
            l += __shfl_xor_sync(0xffffffffu, l, 1);
            l += __shfl_xor_sync(0xffffffffu, l, 2);
            w += __shfl_xor_sync(0xffffffffu, w, 1);
            w += __shfl_xor_sync(0xffffffffu, w, 2);
            if (tig == 0) {
                int row = warpM * 32 + mt * 16 + g + rh * 8;
                part[row * 2 + warpN] = make_float4(m, l, w, 0.f);
            }
        }
    __syncthreads();
    if (tid < 128) {
        float4 p0 = part[tid * 2 + 0];
        float4 p1 = part[tid * 2 + 1];
        float nm = fmaxf(p0.x, p1.x);
        float e0 = __expf(p0.x - nm);
        float e1 = __expf(p1.x - nm);
        g_tpart[(((size_t)b * 8 + vt) * 4 + tt) * 128 + tid] =
            make_float4(nm, p0.y * e0 + p1.y * e1, p0.z * e0 + p1.z * e1, 0.f);
    }
#undef COPY_NEXT
}

// ======================= merge: combine t-tile partials ====================
__global__ __launch_bounds__(128) void merge_kernel(const int* __restrict__ lens,
                                                    const float* __restrict__ b_score,
                                                    float* __restrict__ y_utts) {
    const int b = blockIdx.y, vt = blockIdx.x, row = threadIdx.x;
    const int nt = (lens[b] + 127) >> 7;
    const float4* src = g_tpart + ((size_t)b * 8 + vt) * 4 * 128 + row;
    float m = -CUDART_INF_F, l = 0.f, w = 0.f;
    for (int tt = 0; tt < nt; tt++) {
        float4 p = src[(size_t)tt * 128];
        float nm = fmaxf(m, p.x);
        float sc = __expf(m - nm);
        float e  = __expf(p.x - nm);
        l = l * sc + p.y * e;
        w = w * sc + p.z * e;
        m = nm;
    }
    y_utts[b * V_ + vt * 128 + row] = w / l + b_score[0];
}

// ======================= acts: s2 dot (warp per (b,a)) =====================
__global__ __launch_bounds__(256) void acts_s2_kernel(const float* __restrict__ C_acts,
                                                      const float* __restrict__ c_utt) {
    const int gw = blockIdx.x * 8 + (threadIdx.x >> 5);
    const int lane = threadIdx.x & 31;
    const int b = gw >> 7, a = gw & 127;
    const float4* cr = (const float4*)(C_acts + ((size_t)b * A_ + a) * D_);
    const float4* cu = (const float4*)(c_utt + (size_t)b * D_);
    float s = 0.f;
    for (int i = lane; i < D_ / 4; i += 32) {
        float4 x = cr[i], y = cu[i];
        s += x.x * y.x + x.y * y.y + x.z * y.z + x.w * y.w;
    }
#pragma unroll
    for (int o = 16; o; o >>= 1) s += __shfl_xor_sync(0xffffffffu, s, o);
    if (lane == 0) g_p[gw] = s;
}

// ======================= acts: softmax over a ==============================
__global__ __launch_bounds__(128) void acts_softmax_kernel() {
    __shared__ float w4[4], w4b[4];
    const int b = blockIdx.x;
    const int tid = threadIdx.x;
    const int warp = tid >> 5, lane = tid & 31;
    float s = g_p[b * A_ + tid];
    float m = s;
#pragma unroll
    for (int o = 16; o; o >>= 1) m = fmaxf(m, __shfl_xor_sync(0xffffffffu, m, o));
    if (lane == 0) w4[warp] = m;
    __syncthreads();
    m = fmaxf(fmaxf(w4[0], w4[1]), fmaxf(w4[2], w4[3]));
    float e = __expf(s - m);
    float smv = e;
#pragma unroll
    for (int o = 16; o; o >>= 1) smv += __shfl_xor_sync(0xffffffffu, smv, o);
    if (lane == 0) w4b[warp] = smv;
    __syncthreads();
    float tot = w4b[0] + w4b[1] + w4b[2] + w4b[3];
    g_p[b * A_ + tid] = e / tot;
}

// ======================= acts phase B: q = p @ C_acts ======================
__global__ __launch_bounds__(128) void acts_q_kernel(const float* __restrict__ C_acts) {
    __shared__ float p[A_];
    const int b = blockIdx.y;
    const int d = blockIdx.x * 100 + threadIdx.x;
    if (threadIdx.x < A_) p[threadIdx.x] = g_p[b * A_ + threadIdx.x];
    __syncthreads();
    if (threadIdx.x >= 100) return;
    const float* Cb = C_acts + (size_t)b * A_ * D_ + d;
    float q = 0.f;
#pragma unroll 4
    for (int a = 0; a < A_; a++) q = fmaf(p[a], Cb[(size_t)a * D_], q);
    g_q[b * D_ + d] = q;
}

// ======================= y_acts: warp per v-row ============================
__global__ __launch_bounds__(256) void yacts_kernel(const float* __restrict__ vals,
                                                    float* __restrict__ y_acts) {
    __shared__ float qs[16 * D_];
    const int tid = threadIdx.x, lane = tid & 31, wid = tid >> 5;
    const int b0 = blockIdx.y * 16;
    const int v = blockIdx.x * 8 + wid;

    for (int f = tid; f < 16 * D_; f += 256) qs[f] = g_q[b0 * D_ + f];
    __syncthreads();

    float acc[16];
#pragma unroll
    for (int bb = 0; bb < 16; bb++) acc[bb] = 0.f;

    const float4* vr = (const float4*)(vals + (size_t)v * D_);
    const float4* q4 = (const float4*)qs;
    for (int d4 = lane; d4 < D_ / 4; d4 += 32) {
        float4 r = vr[d4];
#pragma unroll
        for (int bb = 0; bb < 16; bb++) {
            float4 q = q4[bb * (D_ / 4) + d4];
            acc[bb] += r.x * q.x + r.y * q.y + r.z * q.z + r.w * q.w;
        }
    }
#pragma unroll
    for (int o = 16; o; o >>= 1)
#pragma unroll
        for (int bb = 0; bb < 16; bb++)
            acc[bb] += __shfl_xor_sync(0xffffffffu, acc[bb], o);
    if (lane == 0) {
#pragma unroll
        for (int bb = 0; bb < 16; bb++)
            y_acts[(size_t)(b0 + bb) * V_ + v] = acc[bb];
    }
}

// ===========================================================================
extern "C" void kernel_launch(void* const* d_in, const int* in_sizes, int n_in,
                              void* d_out, int out_size) {
    const float* H       = (const float*)d_in[0];
    const float* c_utt   = (const float*)d_in[1];
    const float* C_acts  = (const float*)d_in[2];
    const float* C_vals  = (const float*)d_in[3];
    const float* W       = (const float*)d_in[4];
    const float* b_score = (const float*)d_in[5];
    const int*   lens    = (const int*)d_in[6];

    float* y_utts = (float*)d_out;
    float* y_acts = (float*)d_out + (size_t)B_ * V_;

    static cudaStream_t sS = nullptr, sT = nullptr, sV = nullptr;
    static cudaEvent_t evFork = nullptr, evPrep1 = nullptr, evV = nullptr,
                       evS = nullptr, evT = nullptr;
    if (!sS) {
        cudaStreamCreateWithFlags(&sS, cudaStreamNonBlocking);
        cudaStreamCreateWithFlags(&sT, cudaStreamNonBlocking);
        cudaStreamCreateWithFlags(&sV, cudaStreamNonBlocking);
        cudaEventCreateWithFlags(&evFork, cudaEventDisableTiming);
        cudaEventCreateWithFlags(&evPrep1, cudaEventDisableTiming);
        cudaEventCreateWithFlags(&evV, cudaEventDisableTiming);
        cudaEventCreateWithFlags(&evS, cudaEventDisableTiming);
        cudaEventCreateWithFlags(&evT, cudaEventDisableTiming);
        cudaFuncSetAttribute(fused_kernel,
                             cudaFuncAttributeMaxDynamicSharedMemorySize, SMEM_BYTES);
    }

    cudaEventRecord(evFork, 0);
    cudaStreamWaitEvent(sT, evFork, 0);
    cudaStreamWaitEvent(sV, evFork, 0);

    // V split overlaps sort + prep1
    split_v_kernel<<<V_ / 8, 256, 0, sV>>>(C_vals);
    cudaEventRecord(evV, sV);

    // main: sort/enumerate -> prep half 1 (LPT ranks 0..63) -> fused half 1
    sort_kernel<<<1, B_>>>(lens);
    prep_h_kernel<<<(HB_ * T_) / 8, 256>>>(H, W, lens, 0);
    cudaEventRecord(evPrep1, 0);
    cudaStreamWaitEvent(0, evV, 0);
    fused_kernel<<<MAXI_HALF, 256, SMEM_BYTES>>>(lens, 0);

    // side S: prep half 2 overlaps fused1; fused half 2 backfills
    cudaStreamWaitEvent(sS, evPrep1, 0);
    cudaStreamWaitEvent(sS, evV, 0);
    prep_h_kernel<<<(HB_ * T_) / 8, 256, 0, sS>>>(H, W, lens, HB_);
    fused_kernel<<<MAXI_HALF, 256, SMEM_BYTES, sS>>>(lens, 1);
    cudaEventRecord(evS, sS);

    // merge after both halves
    cudaStreamWaitEvent(0, evS, 0);
    merge_kernel<<<dim3(8, B_), 128>>>(lens, b_score, y_utts);

    // acts chain on stream T (independent)
    acts_s2_kernel<<<B_ * A_ / 8, 256, 0, sT>>>(C_acts, c_utt);
    acts_softmax_kernel<<<B_, 128, 0, sT>>>();
    acts_q_kernel<<<dim3(4, B_), 128, 0, sT>>>(C_acts);
    yacts_kernel<<<dim3(V_ / 8, B_ / 16), 256, 0, sT>>>(C_vals, y_acts);
    cudaEventRecord(evT, sT);

    cudaStreamWaitEvent(0, evT, 0);
}